// round 8
// baseline (speedup 1.0000x reference)
#include <cuda_runtime.h>
#include <cuda_fp16.h>
#include <math.h>
#include <stdint.h>

#define NB   4096
#define NE   16
#define DI   1024
#define DH   2048
#define DOUT 1024
#define NSLOT (NB * 2)
#define MAXT 80          // max 128-row m-tiles across experts (<=79, pad 80)

// ---------------- scratch ----------------------------------------------------
__device__ __half g_h[(size_t)NSLOT * DH];         // fp16 hidden activations
__device__ float  g_contrib[(size_t)NSLOT * DOUT];
__device__ int    g_perm[NSLOT];
__device__ int    g_inv[NSLOT];
__device__ int    g_counts[NE];
__device__ int    g_cursor[NE];
__device__ int    g_off[NE + 1];
__device__ int    g_tidx[NB * 2];
__device__ float  g_tw[NB * 2];
__device__ int    g_tile_e[MAXT];
__device__ int    g_tile_m[MAXT];

// ---------------- helpers ----------------------------------------------------
__device__ __forceinline__ void ldsm4(uint32_t addr, uint32_t* a) {
    asm volatile("ldmatrix.sync.aligned.m8n8.x4.shared.b16 {%0,%1,%2,%3}, [%4];"
                 : "=r"(a[0]), "=r"(a[1]), "=r"(a[2]), "=r"(a[3]) : "r"(addr));
}
__device__ __forceinline__ void mma_f16(float* d, const uint32_t* a, const uint32_t* b) {
    asm volatile(
        "mma.sync.aligned.m16n8k16.row.col.f32.f16.f16.f32 "
        "{%0,%1,%2,%3}, {%4,%5,%6,%7}, {%8,%9}, {%0,%1,%2,%3};"
        : "+f"(d[0]), "+f"(d[1]), "+f"(d[2]), "+f"(d[3])
        : "r"(a[0]), "r"(a[1]), "r"(a[2]), "r"(a[3]), "r"(b[0]), "r"(b[1]));
}
__device__ __forceinline__ uint32_t h2bits(__half2 h) {
    return *reinterpret_cast<uint32_t*>(&h);
}
__device__ __forceinline__ uint2 cvt2h(float4 v) {
    uint2 u;
    u.x = h2bits(__floats2half2_rn(v.x, v.y));
    u.y = h2bits(__floats2half2_rn(v.z, v.w));
    return u;
}

// ---------------- init -------------------------------------------------------
__global__ void init_kernel() {
    int t = threadIdx.x;
    if (t < NE) { g_counts[t] = 0; g_cursor[t] = 0; }
}

// ---------------- gate (fp32 exact — routing must match reference) -----------
__global__ __launch_bounds__(128) void gate_kernel(const float* __restrict__ x,
                                                   const float* __restrict__ gw) {
    __shared__ float xs[4][DI];
    __shared__ float sc[4][NE];
    int t0 = blockIdx.x * 4;

    const float4* xsrc = (const float4*)(x + (size_t)t0 * DI);
    float4* xd = (float4*)&xs[0][0];
    #pragma unroll 4
    for (int i = threadIdx.x; i < 4 * DI / 4; i += 128) xd[i] = xsrc[i];
    __syncthreads();

    int warp = threadIdx.x >> 5, lane = threadIdx.x & 31;
    for (int e = warp * 4; e < warp * 4 + 4; ++e) {
        float s0 = 0.f, s1 = 0.f, s2 = 0.f, s3 = 0.f;
        for (int i = lane; i < DI; i += 32) {
            float g = gw[e * DI + i];
            s0 += xs[0][i] * g; s1 += xs[1][i] * g;
            s2 += xs[2][i] * g; s3 += xs[3][i] * g;
        }
        #pragma unroll
        for (int o = 16; o > 0; o >>= 1) {
            s0 += __shfl_xor_sync(0xffffffffu, s0, o);
            s1 += __shfl_xor_sync(0xffffffffu, s1, o);
            s2 += __shfl_xor_sync(0xffffffffu, s2, o);
            s3 += __shfl_xor_sync(0xffffffffu, s3, o);
        }
        if (lane == 0) { sc[0][e] = s0; sc[1][e] = s1; sc[2][e] = s2; sc[3][e] = s3; }
    }
    __syncthreads();

    if (threadIdx.x < 4) {
        int tt = threadIdx.x;
        int tok = t0 + tt;
        float bv = -1e30f; int bi = 0;
        #pragma unroll
        for (int e = 0; e < NE; ++e) {
            float v = sc[tt][e];
            if (v > bv) { bv = v; bi = e; }
        }
        float bv2 = -1e30f; int bi2 = 0;
        #pragma unroll
        for (int e = 0; e < NE; ++e) {
            if (e == bi) continue;
            float v = sc[tt][e];
            if (v > bv2) { bv2 = v; bi2 = e; }
        }
        float e2 = expf(bv2 - bv);
        float inv = 1.0f / (1.0f + e2);
        g_tidx[tok * 2 + 0] = bi;  g_tw[tok * 2 + 0] = inv;
        g_tidx[tok * 2 + 1] = bi2; g_tw[tok * 2 + 1] = e2 * inv;
        atomicAdd(&g_counts[bi], 1);
        atomicAdd(&g_counts[bi2], 1);
    }
}

// ---------------- prefix + exact tile table ----------------------------------
__global__ void prefix_kernel() {
    if (threadIdx.x == 0) {
        int s = 0;
        #pragma unroll
        for (int e = 0; e < NE; ++e) { g_off[e] = s; s += g_counts[e]; }
        g_off[NE] = s;
        int nt = 0;
        for (int e = 0; e < NE; ++e)
            for (int m = g_off[e]; m < g_off[e + 1]; m += 128) {
                g_tile_e[nt] = e; g_tile_m[nt] = m; ++nt;
            }
        for (; nt < MAXT; ++nt) g_tile_e[nt] = -1;
    }
}

// ---------------- scatter (two-level, low contention) -------------------------
__global__ __launch_bounds__(256) void scatter_kernel() {
    __shared__ int lcnt[NE];
    __shared__ int lbase[NE];
    int tid = threadIdx.x;
    int tok = blockIdx.x * 256 + tid;
    if (tid < NE) lcnt[tid] = 0;
    __syncthreads();
    int e0 = g_tidx[tok * 2 + 0], e1 = g_tidx[tok * 2 + 1];
    int r0 = atomicAdd(&lcnt[e0], 1);
    int r1 = atomicAdd(&lcnt[e1], 1);
    __syncthreads();
    if (tid < NE) lbase[tid] = atomicAdd(&g_cursor[tid], lcnt[tid]);
    __syncthreads();
    int p0 = g_off[e0] + lbase[e0] + r0;
    int p1 = g_off[e1] + lbase[e1] + r1;
    g_perm[p0] = tok * 2 + 0;  g_inv[tok * 2 + 0] = p0;
    g_perm[p1] = tok * 2 + 1;  g_inv[tok * 2 + 1] = p1;
}

// ---------------- fp16 mma.sync grouped GEMM: CTA 128x256, warp 64x64 ---------
// 8 warps (2m x 4n). BK=32, double-buffered, convert-on-load (R6 datapath).
// MODE 0: g_h = relu(gather(x) @ w1^T + b1)        (K=DI,  NTOT=DH, A fp32)
// MODE 1: g_contrib = (g_h @ w2^T + b2) * gate_w   (K=DH,  NTOT=DOUT, A fp16)
#define TS 40
#define ABUF_H   (128 * TS)                  // A tile halfs
#define BBUF_H   (256 * TS)                  // B tile halfs
#define STAGE_H  (ABUF_H + BBUF_H)
#define GEMM_SMEM (2 * STAGE_H * 2)          // 61440 bytes

template <int K, int NTOT, int MODE>
__global__ __launch_bounds__(256, 1) void gemm_tc(const float* __restrict__ Ap,
                                                  const float* __restrict__ W,
                                                  const float* __restrict__ bias) {
    extern __shared__ __half smh[];
    __shared__ float bias_s[256];

    const int NC = K / 32;

    int e = g_tile_e[blockIdx.y];
    if (e < 0) return;
    int m0 = g_tile_m[blockIdx.y];
    int mEnd = g_off[e + 1];
    int n0 = blockIdx.x * 256;

    int tid = threadIdx.x, lane = tid & 31, wid = tid >> 5;
    int mw = (wid >> 2) * 64;        // 2 warps in m
    int nw = (wid & 3) * 64;         // 4 warps in n, 64 wide

    bias_s[tid] = bias[e * NTOT + n0 + tid];

    // ---- loader mapping: rowA/rowB0 = tid>>1 (0..127), seg = (tid&1)*16 elems
    int lrow = tid >> 1;
    int seg = (tid & 1) * 16;
    int sOffA = lrow * TS + seg;                   // A halfs offset
    int sOffB0 = lrow * TS + seg;                  // B row lrow
    int sOffB1 = (lrow + 128) * TS + seg;          // B row lrow+128

    const float* bP0 = W + (size_t)e * NTOT * K + (size_t)(n0 + lrow) * K + seg;
    const float* bP1 = W + (size_t)e * NTOT * K + (size_t)(n0 + lrow + 128) * K + seg;

    const float* aPf = nullptr;
    const __half* aPh = nullptr;
    {
        int gRow = m0 + lrow;
        int cRow = (gRow < mEnd) ? gRow : m0;
        if (MODE == 0) {
            int pair = g_perm[cRow];
            aPf = Ap + (size_t)(pair >> 1) * K + seg;
        } else {
            aPh = g_h + (size_t)cRow * K + seg;
        }
    }

    // ---- fragment addressing
    uint32_t sb = (uint32_t)__cvta_generic_to_shared(smh);
    uint32_t aAddrBase = sb + (uint32_t)(((mw + (lane & 15)) * TS + (lane >> 4) * 8) * 2);
    int bg = lane >> 3;                     // (nblk, khalf)
    int nblk = bg >> 1, khalf = bg & 1;
    uint32_t bAddrBase = sb + (uint32_t)((ABUF_H +
        (nw + nblk * 8 + (lane & 7)) * TS + khalf * 8) * 2);

    float acc[4][8][4];
    #pragma unroll
    for (int mi = 0; mi < 4; ++mi)
        #pragma unroll
        for (int ni = 0; ni < 8; ++ni)
            #pragma unroll
            for (int j = 0; j < 4; ++j) acc[mi][ni][j] = 0.f;

    // prefetch registers (converted to fp16 at fetch)
    uint2 ha[4];     // MODE 0: 16 floats of A
    uint4 qa[2];     // MODE 1: 16 halfs of A (raw copy)
    uint2 hb[8];     // 2 B rows x 16 floats

    // ---- fetch chunk 0
    #pragma unroll
    for (int i = 0; i < 4; ++i) {
        hb[i]     = cvt2h(*(const float4*)(bP0 + i * 4));
        hb[4 + i] = cvt2h(*(const float4*)(bP1 + i * 4));
    }
    if (MODE == 0) {
        #pragma unroll
        for (int i = 0; i < 4; ++i) ha[i] = cvt2h(*(const float4*)(aPf + i * 4));
    } else {
        qa[0] = *(const uint4*)(aPh);
        qa[1] = *(const uint4*)(aPh + 8);
    }
    // ---- store chunk 0 -> buffer 0
    {
        __half* sA = smh;
        __half* sB = smh + ABUF_H;
        *(uint4*)(sB + sOffB0)     = make_uint4(hb[0].x, hb[0].y, hb[1].x, hb[1].y);
        *(uint4*)(sB + sOffB0 + 8) = make_uint4(hb[2].x, hb[2].y, hb[3].x, hb[3].y);
        *(uint4*)(sB + sOffB1)     = make_uint4(hb[4].x, hb[4].y, hb[5].x, hb[5].y);
        *(uint4*)(sB + sOffB1 + 8) = make_uint4(hb[6].x, hb[6].y, hb[7].x, hb[7].y);
        if (MODE == 0) {
            *(uint4*)(sA + sOffA)     = make_uint4(ha[0].x, ha[0].y, ha[1].x, ha[1].y);
            *(uint4*)(sA + sOffA + 8) = make_uint4(ha[2].x, ha[2].y, ha[3].x, ha[3].y);
        } else {
            *(uint4*)(sA + sOffA)     = qa[0];
            *(uint4*)(sA + sOffA + 8) = qa[1];
        }
    }
    __syncthreads();

    for (int s = 0; s < NC; ++s) {
        int b = s & 1;
        if (s + 1 < NC) {
            #pragma unroll
            for (int i = 0; i < 4; ++i) {
                hb[i]     = cvt2h(*(const float4*)(bP0 + (s + 1) * 32 + i * 4));
                hb[4 + i] = cvt2h(*(const float4*)(bP1 + (s + 1) * 32 + i * 4));
            }
            if (MODE == 0) {
                #pragma unroll
                for (int i = 0; i < 4; ++i)
                    ha[i] = cvt2h(*(const float4*)(aPf + (s + 1) * 32 + i * 4));
            } else {
                qa[0] = *(const uint4*)(aPh + (s + 1) * 32);
                qa[1] = *(const uint4*)(aPh + (s + 1) * 32 + 8);
            }
        }
        // ---- compute on buffer b
        uint32_t aA = aAddrBase + (uint32_t)(b * STAGE_H * 2);
        uint32_t bA = bAddrBase + (uint32_t)(b * STAGE_H * 2);
        #pragma unroll
        for (int ks = 0; ks < 2; ++ks) {
            uint32_t af[4][4];
            #pragma unroll
            for (int mi = 0; mi < 4; ++mi)
                ldsm4(aA + mi * (16 * TS * 2) + ks * 32, af[mi]);
            uint32_t bfr[16];
            #pragma unroll
            for (int ni2 = 0; ni2 < 4; ++ni2)
                ldsm4(bA + ni2 * (16 * TS * 2) + ks * 32, &bfr[ni2 * 4]);
            #pragma unroll
            for (int mi = 0; mi < 4; ++mi)
                #pragma unroll
                for (int ni = 0; ni < 8; ++ni)
                    mma_f16(acc[mi][ni], af[mi], &bfr[ni * 2]);
        }
        if (s + 1 < NC) {
            int nb = b ^ 1;
            __half* sA = smh + nb * STAGE_H;
            __half* sB = sA + ABUF_H;
            *(uint4*)(sB + sOffB0)     = make_uint4(hb[0].x, hb[0].y, hb[1].x, hb[1].y);
            *(uint4*)(sB + sOffB0 + 8) = make_uint4(hb[2].x, hb[2].y, hb[3].x, hb[3].y);
            *(uint4*)(sB + sOffB1)     = make_uint4(hb[4].x, hb[4].y, hb[5].x, hb[5].y);
            *(uint4*)(sB + sOffB1 + 8) = make_uint4(hb[6].x, hb[6].y, hb[7].x, hb[7].y);
            if (MODE == 0) {
                *(uint4*)(sA + sOffA)     = make_uint4(ha[0].x, ha[0].y, ha[1].x, ha[1].y);
                *(uint4*)(sA + sOffA + 8) = make_uint4(ha[2].x, ha[2].y, ha[3].x, ha[3].y);
            } else {
                *(uint4*)(sA + sOffA)     = qa[0];
                *(uint4*)(sA + sOffA + 8) = qa[1];
            }
            __syncthreads();
        }
    }

    // ---- epilogue
    int r4 = lane >> 2, cc = (lane & 3) * 2;
    #pragma unroll
    for (int mi = 0; mi < 4; ++mi) {
        int row0 = m0 + mw + mi * 16 + r4;
        int row1 = row0 + 8;
        bool v0 = row0 < mEnd, v1 = row1 < mEnd;
        if (MODE == 0) {
            __half* C0 = g_h + (size_t)row0 * NTOT + n0;
            __half* C1 = g_h + (size_t)row1 * NTOT + n0;
            #pragma unroll
            for (int ni = 0; ni < 8; ++ni) {
                int col = nw + ni * 8 + cc;
                float bb0 = bias_s[col], bb1 = bias_s[col + 1];
                const float* d = acc[mi][ni];
                if (v0) {
                    __half2 h = __floats2half2_rn(fmaxf(d[0] + bb0, 0.f),
                                                  fmaxf(d[1] + bb1, 0.f));
                    *(__half2*)&C0[col] = h;
                }
                if (v1) {
                    __half2 h = __floats2half2_rn(fmaxf(d[2] + bb0, 0.f),
                                                  fmaxf(d[3] + bb1, 0.f));
                    *(__half2*)&C1[col] = h;
                }
            }
        } else {
            float w0 = 1.f, w1 = 1.f;
            if (v0) w0 = g_tw[g_perm[row0]];
            if (v1) w1 = g_tw[g_perm[row1]];
            float* C0 = g_contrib + (size_t)row0 * NTOT + n0;
            float* C1 = g_contrib + (size_t)row1 * NTOT + n0;
            #pragma unroll
            for (int ni = 0; ni < 8; ++ni) {
                int col = nw + ni * 8 + cc;
                float bb0 = bias_s[col], bb1 = bias_s[col + 1];
                const float* d = acc[mi][ni];
                if (v0) {
                    float2 o; o.x = (d[0] + bb0) * w0; o.y = (d[1] + bb1) * w0;
                    *(float2*)&C0[col] = o;
                }
                if (v1) {
                    float2 o; o.x = (d[2] + bb0) * w1; o.y = (d[3] + bb1) * w1;
                    *(float2*)&C1[col] = o;
                }
            }
        }
    }
}

// ---------------- combine ----------------------------------------------------
__global__ __launch_bounds__(256) void combine_kernel(float* __restrict__ out) {
    int idx = blockIdx.x * 256 + threadIdx.x;
    int tok = idx >> 8;
    int d4 = idx & 255;
    const float4* c0 = (const float4*)&g_contrib[(size_t)g_inv[tok * 2 + 0] * DOUT];
    const float4* c1 = (const float4*)&g_contrib[(size_t)g_inv[tok * 2 + 1] * DOUT];
    float4 a = c0[d4], b = c1[d4];
    float4 r;
    r.x = a.x + b.x; r.y = a.y + b.y; r.z = a.z + b.z; r.w = a.w + b.w;
    ((float4*)out)[idx] = r;
}

// ---------------- launch -----------------------------------------------------
extern "C" void kernel_launch(void* const* d_in, const int* in_sizes, int n_in,
                              void* d_out, int out_size) {
    const float* x  = (const float*)d_in[0];
    const float* gw = (const float*)d_in[1];
    const float* w1 = (const float*)d_in[2];
    const float* b1 = (const float*)d_in[3];
    const float* w2 = (const float*)d_in[4];
    const float* b2 = (const float*)d_in[5];
    float* out = (float*)d_out;

    cudaFuncSetAttribute(gemm_tc<DI, DH, 0>,
                         cudaFuncAttributeMaxDynamicSharedMemorySize, GEMM_SMEM);
    cudaFuncSetAttribute(gemm_tc<DH, DOUT, 1>,
                         cudaFuncAttributeMaxDynamicSharedMemorySize, GEMM_SMEM);

    init_kernel<<<1, 32>>>();
    gate_kernel<<<NB / 4, 128>>>(x, gw);
    prefix_kernel<<<1, 32>>>();
    scatter_kernel<<<NB / 256, 256>>>();
    gemm_tc<DI, DH, 0><<<dim3(DH / 256, MAXT), 256, GEMM_SMEM>>>(x, w1, b1);
    gemm_tc<DH, DOUT, 1><<<dim3(DOUT / 256, MAXT), 256, GEMM_SMEM>>>(nullptr, w2, b2);
    combine_kernel<<<NB * (DOUT / 4) / 256, 256>>>(out);
}

// round 9
// speedup vs baseline: 1.3962x; 1.3962x over previous
#include <cuda_runtime.h>
#include <cuda_fp16.h>
#include <math.h>
#include <stdint.h>

#define NB   4096
#define NE   16
#define DI   1024
#define DH   2048
#define DOUT 1024
#define NSLOT (NB * 2)
#define MAXT 80          // max 128-row m-tiles across experts (<=79, pad 80)
#define XCB  128         // x fp32->fp16 converter blocks (appended to scatter grid)
#define W2CY 8           // extra grid.y rows of w2 converters inside GEMM1

// ---------------- scratch ----------------------------------------------------
__device__ __half g_xh[(size_t)NB * DI];           // fp16 x
__device__ __half g_w2h[(size_t)NE * DOUT * DH];   // fp16 w2
__device__ __half g_h[(size_t)NSLOT * DH];         // fp16 hidden activations
__device__ float  g_contrib[(size_t)NSLOT * DOUT];
__device__ int    g_perm[NSLOT];
__device__ int    g_inv[NSLOT];
__device__ int    g_counts[NE];
__device__ int    g_cursor[NE];
__device__ int    g_off[NE + 1];
__device__ int    g_tidx[NB * 2];
__device__ float  g_tw[NB * 2];
__device__ int    g_tile_e[MAXT];
__device__ int    g_tile_m[MAXT];

// ---------------- helpers ----------------------------------------------------
__device__ __forceinline__ void ldsm4(uint32_t addr, uint32_t* a) {
    asm volatile("ldmatrix.sync.aligned.m8n8.x4.shared.b16 {%0,%1,%2,%3}, [%4];"
                 : "=r"(a[0]), "=r"(a[1]), "=r"(a[2]), "=r"(a[3]) : "r"(addr));
}
__device__ __forceinline__ void mma_f16(float* d, const uint32_t* a, const uint32_t* b) {
    asm volatile(
        "mma.sync.aligned.m16n8k16.row.col.f32.f16.f16.f32 "
        "{%0,%1,%2,%3}, {%4,%5,%6,%7}, {%8,%9}, {%0,%1,%2,%3};"
        : "+f"(d[0]), "+f"(d[1]), "+f"(d[2]), "+f"(d[3])
        : "r"(a[0]), "r"(a[1]), "r"(a[2]), "r"(a[3]), "r"(b[0]), "r"(b[1]));
}
__device__ __forceinline__ uint32_t h2bits(__half2 h) {
    return *reinterpret_cast<uint32_t*>(&h);
}
__device__ __forceinline__ uint2 cvt2h(float4 v) {
    uint2 u;
    u.x = h2bits(__floats2half2_rn(v.x, v.y));
    u.y = h2bits(__floats2half2_rn(v.z, v.w));
    return u;
}
__device__ __forceinline__ void cp16cg(uint32_t dst, const void* src) {
    asm volatile("cp.async.cg.shared.global [%0], [%1], 16;" :: "r"(dst), "l"(src));
}
__device__ __forceinline__ void cp_commit() {
    asm volatile("cp.async.commit_group;" ::: "memory");
}
template <int N>
__device__ __forceinline__ void cp_wait() {
    asm volatile("cp.async.wait_group %0;" :: "n"(N) : "memory");
}

// ---------------- init -------------------------------------------------------
__global__ void init_kernel() {
    int t = threadIdx.x;
    if (t < NE) { g_counts[t] = 0; g_cursor[t] = 0; }
}

// ---------------- gate (fp32 exact — routing must match reference) -----------
__global__ __launch_bounds__(128) void gate_kernel(const float* __restrict__ x,
                                                   const float* __restrict__ gw) {
    __shared__ float xs[4][DI];
    __shared__ float sc[4][NE];
    int t0 = blockIdx.x * 4;

    const float4* xsrc = (const float4*)(x + (size_t)t0 * DI);
    float4* xd = (float4*)&xs[0][0];
    #pragma unroll 4
    for (int i = threadIdx.x; i < 4 * DI / 4; i += 128) xd[i] = xsrc[i];
    __syncthreads();

    int warp = threadIdx.x >> 5, lane = threadIdx.x & 31;
    for (int e = warp * 4; e < warp * 4 + 4; ++e) {
        float s0 = 0.f, s1 = 0.f, s2 = 0.f, s3 = 0.f;
        for (int i = lane; i < DI; i += 32) {
            float g = gw[e * DI + i];
            s0 += xs[0][i] * g; s1 += xs[1][i] * g;
            s2 += xs[2][i] * g; s3 += xs[3][i] * g;
        }
        #pragma unroll
        for (int o = 16; o > 0; o >>= 1) {
            s0 += __shfl_xor_sync(0xffffffffu, s0, o);
            s1 += __shfl_xor_sync(0xffffffffu, s1, o);
            s2 += __shfl_xor_sync(0xffffffffu, s2, o);
            s3 += __shfl_xor_sync(0xffffffffu, s3, o);
        }
        if (lane == 0) { sc[0][e] = s0; sc[1][e] = s1; sc[2][e] = s2; sc[3][e] = s3; }
    }
    __syncthreads();

    if (threadIdx.x < 4) {
        int tt = threadIdx.x;
        int tok = t0 + tt;
        float bv = -1e30f; int bi = 0;
        #pragma unroll
        for (int e = 0; e < NE; ++e) {
            float v = sc[tt][e];
            if (v > bv) { bv = v; bi = e; }
        }
        float bv2 = -1e30f; int bi2 = 0;
        #pragma unroll
        for (int e = 0; e < NE; ++e) {
            if (e == bi) continue;
            float v = sc[tt][e];
            if (v > bv2) { bv2 = v; bi2 = e; }
        }
        float e2 = expf(bv2 - bv);
        float inv = 1.0f / (1.0f + e2);
        g_tidx[tok * 2 + 0] = bi;  g_tw[tok * 2 + 0] = inv;
        g_tidx[tok * 2 + 1] = bi2; g_tw[tok * 2 + 1] = e2 * inv;
        atomicAdd(&g_counts[bi], 1);
        atomicAdd(&g_counts[bi2], 1);
    }
}

// ---------------- prefix + exact tile table ----------------------------------
__global__ void prefix_kernel() {
    if (threadIdx.x == 0) {
        int s = 0;
        #pragma unroll
        for (int e = 0; e < NE; ++e) { g_off[e] = s; s += g_counts[e]; }
        g_off[NE] = s;
        int nt = 0;
        for (int e = 0; e < NE; ++e)
            for (int m = g_off[e]; m < g_off[e + 1]; m += 128) {
                g_tile_e[nt] = e; g_tile_m[nt] = m; ++nt;
            }
        for (; nt < MAXT; ++nt) g_tile_e[nt] = -1;
    }
}

// ---------------- scatter + x converter ---------------------------------------
__global__ __launch_bounds__(256) void scatter_kernel(const float4* __restrict__ xf4) {
    if (blockIdx.x >= NB / 256) {                    // x fp32 -> fp16 (16MB, ~4us)
        int c = blockIdx.x - NB / 256;
        size_t base = (size_t)c * 256 + threadIdx.x;
        const size_t STRIDE = (size_t)XCB * 256;
        uint2* dst = (uint2*)g_xh;
        #pragma unroll 8
        for (int i = 0; i < (NB * DI / 4) / (XCB * 256); ++i)
            dst[base + i * STRIDE] = cvt2h(xf4[base + i * STRIDE]);
        return;
    }
    __shared__ int lcnt[NE];
    __shared__ int lbase[NE];
    int tid = threadIdx.x;
    int tok = blockIdx.x * 256 + tid;
    if (tid < NE) lcnt[tid] = 0;
    __syncthreads();
    int e0 = g_tidx[tok * 2 + 0], e1 = g_tidx[tok * 2 + 1];
    int r0 = atomicAdd(&lcnt[e0], 1);
    int r1 = atomicAdd(&lcnt[e1], 1);
    __syncthreads();
    if (tid < NE) lbase[tid] = atomicAdd(&g_cursor[tid], lcnt[tid]);
    __syncthreads();
    int p0 = g_off[e0] + lbase[e0] + r0;
    int p1 = g_off[e1] + lbase[e1] + r1;
    g_perm[p0] = tok * 2 + 0;  g_inv[tok * 2 + 0] = p0;
    g_perm[p1] = tok * 2 + 1;  g_inv[tok * 2 + 1] = p1;
}

// ---------------- fp16 mma.sync grouped GEMM (R6 geometry + cp.async.cg) ------
// CTA 128x128, 8 warps (2m x 4n), warp 64x32, BK=32, 2-stage 40KB, 2 CTA/SM.
// MODE 0: g_h = relu(gather(g_xh) @ w1^T + b1)   A fp16 cp.async, B fp32 cvt.
//         blockIdx.y >= MAXT rows convert w2 -> g_w2h (hidden under GEMM).
// MODE 1: g_contrib = (g_h @ g_w2h^T + b2) * gw  A+B fp16 cp.async.
#define TS 40
#define ABUF_H (128 * TS)
#define STAGE_H (2 * ABUF_H)
#define GEMM_SMEM (2 * STAGE_H * 2)   // 40960 bytes

template <int K, int NTOT, int MODE>
__global__ __launch_bounds__(256) void gemm_tc(const float* __restrict__ W,
                                               const float* __restrict__ bias,
                                               const float4* __restrict__ w2f4) {
    if (MODE == 0 && blockIdx.y >= MAXT) {           // w2 fp32 -> fp16 converter
        int cid = (blockIdx.y - MAXT) * gridDim.x + blockIdx.x;   // 0..127
        size_t base = (size_t)cid * 256 + threadIdx.x;
        const size_t STRIDE = (size_t)(W2CY * 16) * 256;
        uint2* dst = (uint2*)g_w2h;
        #pragma unroll 4
        for (int i = 0; i < (NE * DOUT * DH / 4) / (W2CY * 16 * 256); ++i)
            dst[base + i * STRIDE] = cvt2h(w2f4[base + i * STRIDE]);
        return;
    }

    extern __shared__ __half smh[];
    __shared__ float bias_s[128];
    const int NC = K / 32;

    int e = g_tile_e[blockIdx.y];
    if (e < 0) return;
    int m0 = g_tile_m[blockIdx.y];
    int mEnd = g_off[e + 1];
    int n0 = blockIdx.x * 128;

    int tid = threadIdx.x, lane = tid & 31, wid = tid >> 5;
    int mw = (wid >> 2) * 64;
    int nw = (wid & 3) * 32;

    if (tid < 128) bias_s[tid] = bias[e * NTOT + n0 + tid];

    uint32_t sb = (uint32_t)__cvta_generic_to_shared(smh);

    // ---- A loader (fp16, cp.async): row = tid>>1, seg = (tid&1)*16 halfs
    int arow = tid >> 1;
    int aseg = (tid & 1) * 16;
    uint32_t aRowOff = (uint32_t)(arow * TS + aseg) * 2;   // bytes in A tile
    const __half* Ah = (MODE == 0) ? g_xh : g_h;
    int gRowA = m0 + arow;
    int cRowA = (gRowA < mEnd) ? gRowA : m0;
    int aRowIdx = (MODE == 0) ? (g_perm[cRowA] >> 1) : cRowA;
    const __half* aSrc = Ah + (size_t)aRowIdx * K + aseg;

    // ---- B loader
    // MODE 0 (fp32 w1): brow = tid>>3 (+32i), bc4 = tid&7 -> LDG+cvt+STS
    // MODE 1 (fp16 w2): same mapping as A -> cp.async
    int brow = tid >> 3, bc4 = tid & 7;
    const float* bPf[4];
    int bOff[4];
    const __half* bSrcH = nullptr;
    if (MODE == 0) {
        #pragma unroll
        for (int i = 0; i < 4; ++i) {
            int row = brow + 32 * i;
            bPf[i] = W + (size_t)e * NTOT * K + (size_t)(n0 + row) * K + bc4 * 4;
            bOff[i] = row * TS + bc4 * 4;
        }
    } else {
        bSrcH = g_w2h + (size_t)e * NTOT * K + (size_t)(n0 + arow) * K + aseg;
    }

    // ---- fragment addressing (identical to R6)
    uint32_t aAddrBase = sb + (uint32_t)(((mw + (lane & 15)) * TS + (lane >> 4) * 8) * 2);
    int bg = lane >> 3;
    int nblk = bg >> 1, khalf = bg & 1;
    uint32_t bAddrBase = sb + (uint32_t)((ABUF_H +
        (nw + nblk * 8 + (lane & 7)) * TS + khalf * 8) * 2);

    float acc[4][4][4];
    #pragma unroll
    for (int mi = 0; mi < 4; ++mi)
        #pragma unroll
        for (int ni = 0; ni < 4; ++ni)
            #pragma unroll
            for (int j = 0; j < 4; ++j) acc[mi][ni][j] = 0.f;

    float4 pb[4];     // MODE 0 B prefetch (fp32)

    // ---- prologue: stage 0
    {
        cp16cg(sb + aRowOff, aSrc);
        cp16cg(sb + aRowOff + 16, aSrc + 8);
        if (MODE == 1) {
            cp16cg(sb + ABUF_H * 2 + aRowOff, bSrcH);
            cp16cg(sb + ABUF_H * 2 + aRowOff + 16, bSrcH + 8);
        }
        cp_commit();
        if (MODE == 0) {
            __half* sB = smh + ABUF_H;
            #pragma unroll
            for (int i = 0; i < 4; ++i) {
                uint2 u = cvt2h(*(const float4*)(bPf[i]));
                *(uint2*)(sB + bOff[i]) = u;
            }
        }
        cp_wait<0>();
        __syncthreads();
    }

    for (int s = 0; s < NC; ++s) {
        int b = s & 1;
        int nb = b ^ 1;
        // issue next-stage async loads + B register prefetch before compute
        if (s + 1 < NC) {
            uint32_t nbase = sb + nb * STAGE_H * 2;
            cp16cg(nbase + aRowOff, aSrc + (s + 1) * 32);
            cp16cg(nbase + aRowOff + 16, aSrc + (s + 1) * 32 + 8);
            if (MODE == 1) {
                cp16cg(nbase + ABUF_H * 2 + aRowOff, bSrcH + (s + 1) * 32);
                cp16cg(nbase + ABUF_H * 2 + aRowOff + 16, bSrcH + (s + 1) * 32 + 8);
            }
            cp_commit();
            if (MODE == 0) {
                #pragma unroll
                for (int i = 0; i < 4; ++i) pb[i] = *(const float4*)(bPf[i] + (s + 1) * 32);
            }
        }
        // ---- compute buffer b
        uint32_t aA = aAddrBase + (uint32_t)(b * STAGE_H * 2);
        uint32_t bA = bAddrBase + (uint32_t)(b * STAGE_H * 2);
        #pragma unroll
        for (int ks = 0; ks < 2; ++ks) {
            uint32_t af[4][4];
            #pragma unroll
            for (int mi = 0; mi < 4; ++mi)
                ldsm4(aA + mi * (16 * TS * 2) + ks * 32, af[mi]);
            uint32_t bfr[8];
            #pragma unroll
            for (int ni2 = 0; ni2 < 2; ++ni2)
                ldsm4(bA + ni2 * (16 * TS * 2) + ks * 32, &bfr[ni2 * 4]);
            #pragma unroll
            for (int mi = 0; mi < 4; ++mi)
                #pragma unroll
                for (int ni = 0; ni < 4; ++ni)
                    mma_f16(acc[mi][ni], af[mi], &bfr[ni * 2]);
        }
        if (s + 1 < NC) {
            if (MODE == 0) {
                __half* sB = smh + nb * STAGE_H + ABUF_H;
                #pragma unroll
                for (int i = 0; i < 4; ++i) {
                    uint2 u = cvt2h(pb[i]);
                    *(uint2*)(sB + bOff[i]) = u;
                }
            }
            cp_wait<0>();
            __syncthreads();
        }
    }

    // ---- epilogue
    int r4 = lane >> 2, cc = (lane & 3) * 2;
    #pragma unroll
    for (int mi = 0; mi < 4; ++mi) {
        int row0 = m0 + mw + mi * 16 + r4;
        int row1 = row0 + 8;
        bool v0 = row0 < mEnd, v1 = row1 < mEnd;
        if (MODE == 0) {
            __half* C0 = g_h + (size_t)row0 * NTOT + n0;
            __half* C1 = g_h + (size_t)row1 * NTOT + n0;
            #pragma unroll
            for (int ni = 0; ni < 4; ++ni) {
                int col = nw + ni * 8 + cc;
                float bb0 = bias_s[col], bb1 = bias_s[col + 1];
                const float* d = acc[mi][ni];
                if (v0) {
                    __half2 h = __floats2half2_rn(fmaxf(d[0] + bb0, 0.f),
                                                  fmaxf(d[1] + bb1, 0.f));
                    *(__half2*)&C0[col] = h;
                }
                if (v1) {
                    __half2 h = __floats2half2_rn(fmaxf(d[2] + bb0, 0.f),
                                                  fmaxf(d[3] + bb1, 0.f));
                    *(__half2*)&C1[col] = h;
                }
            }
        } else {
            float w0 = 1.f, w1 = 1.f;
            if (v0) w0 = g_tw[g_perm[row0]];
            if (v1) w1 = g_tw[g_perm[row1]];
            float* C0 = g_contrib + (size_t)row0 * NTOT + n0;
            float* C1 = g_contrib + (size_t)row1 * NTOT + n0;
            #pragma unroll
            for (int ni = 0; ni < 4; ++ni) {
                int col = nw + ni * 8 + cc;
                float bb0 = bias_s[col], bb1 = bias_s[col + 1];
                const float* d = acc[mi][ni];
                if (v0) {
                    float2 o; o.x = (d[0] + bb0) * w0; o.y = (d[1] + bb1) * w0;
                    *(float2*)&C0[col] = o;
                }
                if (v1) {
                    float2 o; o.x = (d[2] + bb0) * w1; o.y = (d[3] + bb1) * w1;
                    *(float2*)&C1[col] = o;
                }
            }
        }
    }
}

// ---------------- combine ----------------------------------------------------
__global__ __launch_bounds__(256) void combine_kernel(float* __restrict__ out) {
    int idx = blockIdx.x * 256 + threadIdx.x;
    int tok = idx >> 8;
    int d4 = idx & 255;
    const float4* c0 = (const float4*)&g_contrib[(size_t)g_inv[tok * 2 + 0] * DOUT];
    const float4* c1 = (const float4*)&g_contrib[(size_t)g_inv[tok * 2 + 1] * DOUT];
    float4 a = c0[d4], b = c1[d4];
    float4 r;
    r.x = a.x + b.x; r.y = a.y + b.y; r.z = a.z + b.z; r.w = a.w + b.w;
    ((float4*)out)[idx] = r;
}

// ---------------- launch -----------------------------------------------------
extern "C" void kernel_launch(void* const* d_in, const int* in_sizes, int n_in,
                              void* d_out, int out_size) {
    const float* x  = (const float*)d_in[0];
    const float* gw = (const float*)d_in[1];
    const float* w1 = (const float*)d_in[2];
    const float* b1 = (const float*)d_in[3];
    const float* w2 = (const float*)d_in[4];
    const float* b2 = (const float*)d_in[5];
    float* out = (float*)d_out;

    cudaFuncSetAttribute(gemm_tc<DI, DH, 0>,
                         cudaFuncAttributeMaxDynamicSharedMemorySize, GEMM_SMEM);
    cudaFuncSetAttribute(gemm_tc<DH, DOUT, 1>,
                         cudaFuncAttributeMaxDynamicSharedMemorySize, GEMM_SMEM);

    init_kernel<<<1, 32>>>();
    gate_kernel<<<NB / 4, 128>>>(x, gw);
    prefix_kernel<<<1, 32>>>();
    scatter_kernel<<<NB / 256 + XCB, 256>>>((const float4*)x);
    gemm_tc<DI, DH, 0><<<dim3(DH / 128, MAXT + W2CY), 256, GEMM_SMEM>>>(w1, b1, (const float4*)w2);
    gemm_tc<DH, DOUT, 1><<<dim3(DOUT / 128, MAXT), 256, GEMM_SMEM>>>(nullptr, b2, nullptr);
    combine_kernel<<<NB * (DOUT / 4) / 256, 256>>>(out);
}

// round 10
// speedup vs baseline: 1.4314x; 1.0252x over previous
#include <cuda_runtime.h>
#include <cuda_fp16.h>
#include <math.h>
#include <stdint.h>

#define NB   4096
#define NE   16
#define DI   1024
#define DH   2048
#define DOUT 1024
#define NSLOT (NB * 2)
#define MAXT 80          // max 128-row m-tiles across experts (<=79, pad 80)

// ---------------- scratch ----------------------------------------------------
__device__ __half g_h[(size_t)NSLOT * DH];         // fp16 hidden activations
__device__ float  g_contrib[(size_t)NSLOT * DOUT];
__device__ int    g_perm[NSLOT];
__device__ int    g_inv[NSLOT];
__device__ int    g_counts[NE];
__device__ int    g_cursor[NE];
__device__ int    g_off[NE + 1];
__device__ int    g_tidx[NB * 2];
__device__ float  g_tw[NB * 2];
__device__ int    g_tile_e[MAXT];
__device__ int    g_tile_m[MAXT];

// ---------------- helpers ----------------------------------------------------
__device__ __forceinline__ void ldsm4(uint32_t addr, uint32_t* a) {
    asm volatile("ldmatrix.sync.aligned.m8n8.x4.shared.b16 {%0,%1,%2,%3}, [%4];"
                 : "=r"(a[0]), "=r"(a[1]), "=r"(a[2]), "=r"(a[3]) : "r"(addr));
}
__device__ __forceinline__ void mma_f16(float* d, const uint32_t* a, const uint32_t* b) {
    asm volatile(
        "mma.sync.aligned.m16n8k16.row.col.f32.f16.f16.f32 "
        "{%0,%1,%2,%3}, {%4,%5,%6,%7}, {%8,%9}, {%0,%1,%2,%3};"
        : "+f"(d[0]), "+f"(d[1]), "+f"(d[2]), "+f"(d[3])
        : "r"(a[0]), "r"(a[1]), "r"(a[2]), "r"(a[3]), "r"(b[0]), "r"(b[1]));
}
__device__ __forceinline__ uint32_t h2bits(__half2 h) {
    return *reinterpret_cast<uint32_t*>(&h);
}
__device__ __forceinline__ uint2 cvt2h(float4 v) {
    uint2 u;
    u.x = h2bits(__floats2half2_rn(v.x, v.y));
    u.y = h2bits(__floats2half2_rn(v.z, v.w));
    return u;
}

// ---------------- init -------------------------------------------------------
__global__ void init_kernel() {
    int t = threadIdx.x;
    if (t < NE) { g_counts[t] = 0; g_cursor[t] = 0; }
}

// ---------------- gate (fp32 exact — routing must match reference) -----------
__global__ __launch_bounds__(128) void gate_kernel(const float* __restrict__ x,
                                                   const float* __restrict__ gw) {
    __shared__ float xs[4][DI];
    __shared__ float sc[4][NE];
    int t0 = blockIdx.x * 4;

    const float4* xsrc = (const float4*)(x + (size_t)t0 * DI);
    float4* xd = (float4*)&xs[0][0];
    #pragma unroll 4
    for (int i = threadIdx.x; i < 4 * DI / 4; i += 128) xd[i] = xsrc[i];
    __syncthreads();

    int warp = threadIdx.x >> 5, lane = threadIdx.x & 31;
    for (int e = warp * 4; e < warp * 4 + 4; ++e) {
        float s0 = 0.f, s1 = 0.f, s2 = 0.f, s3 = 0.f;
        for (int i = lane; i < DI; i += 32) {
            float g = gw[e * DI + i];
            s0 += xs[0][i] * g; s1 += xs[1][i] * g;
            s2 += xs[2][i] * g; s3 += xs[3][i] * g;
        }
        #pragma unroll
        for (int o = 16; o > 0; o >>= 1) {
            s0 += __shfl_xor_sync(0xffffffffu, s0, o);
            s1 += __shfl_xor_sync(0xffffffffu, s1, o);
            s2 += __shfl_xor_sync(0xffffffffu, s2, o);
            s3 += __shfl_xor_sync(0xffffffffu, s3, o);
        }
        if (lane == 0) { sc[0][e] = s0; sc[1][e] = s1; sc[2][e] = s2; sc[3][e] = s3; }
    }
    __syncthreads();

    if (threadIdx.x < 4) {
        int tt = threadIdx.x;
        int tok = t0 + tt;
        float bv = -1e30f; int bi = 0;
        #pragma unroll
        for (int e = 0; e < NE; ++e) {
            float v = sc[tt][e];
            if (v > bv) { bv = v; bi = e; }
        }
        float bv2 = -1e30f; int bi2 = 0;
        #pragma unroll
        for (int e = 0; e < NE; ++e) {
            if (e == bi) continue;
            float v = sc[tt][e];
            if (v > bv2) { bv2 = v; bi2 = e; }
        }
        float e2 = expf(bv2 - bv);
        float inv = 1.0f / (1.0f + e2);
        g_tidx[tok * 2 + 0] = bi;  g_tw[tok * 2 + 0] = inv;
        g_tidx[tok * 2 + 1] = bi2; g_tw[tok * 2 + 1] = e2 * inv;
        atomicAdd(&g_counts[bi], 1);
        atomicAdd(&g_counts[bi2], 1);
    }
}

// ---------------- prefix + exact tile table ----------------------------------
__global__ void prefix_kernel() {
    if (threadIdx.x == 0) {
        int s = 0;
        #pragma unroll
        for (int e = 0; e < NE; ++e) { g_off[e] = s; s += g_counts[e]; }
        g_off[NE] = s;
        int nt = 0;
        for (int e = 0; e < NE; ++e)
            for (int m = g_off[e]; m < g_off[e + 1]; m += 128) {
                g_tile_e[nt] = e; g_tile_m[nt] = m; ++nt;
            }
        for (; nt < MAXT; ++nt) g_tile_e[nt] = -1;
    }
}

// ---------------- scatter (two-level, low contention) -------------------------
__global__ __launch_bounds__(256) void scatter_kernel() {
    __shared__ int lcnt[NE];
    __shared__ int lbase[NE];
    int tid = threadIdx.x;
    int tok = blockIdx.x * 256 + tid;
    if (tid < NE) lcnt[tid] = 0;
    __syncthreads();
    int e0 = g_tidx[tok * 2 + 0], e1 = g_tidx[tok * 2 + 1];
    int r0 = atomicAdd(&lcnt[e0], 1);
    int r1 = atomicAdd(&lcnt[e1], 1);
    __syncthreads();
    if (tid < NE) lbase[tid] = atomicAdd(&g_cursor[tid], lcnt[tid]);
    __syncthreads();
    int p0 = g_off[e0] + lbase[e0] + r0;
    int p1 = g_off[e1] + lbase[e1] + r1;
    g_perm[p0] = tok * 2 + 0;  g_inv[tok * 2 + 0] = p0;
    g_perm[p1] = tok * 2 + 1;  g_inv[tok * 2 + 1] = p1;
}

// ---------------- fp16 mma.sync grouped GEMM: 4 warps, warp tile 64x64 --------
// CTA tile 128x128, BK=32, double-buffered 40KB, 2 CTA/SM, 128 threads.
// Same datapath as R6 (LDG + cvt + STS register pipeline).
// MODE 0: g_h = relu(gather(x) @ w1^T + b1)        (K=DI,  NTOT=DH, A fp32)
// MODE 1: g_contrib = (g_h @ w2^T + b2) * gate_w   (K=DH,  NTOT=DOUT, A fp16)
#define TS 40
#define ABUF_H (128 * TS)
#define STAGE_H (2 * ABUF_H)
#define GEMM_SMEM (2 * STAGE_H * 2)   // 40960 bytes

template <int K, int NTOT, int MODE>
__global__ __launch_bounds__(128, 2) void gemm_tc(const float* __restrict__ Ap,
                                                  const float* __restrict__ W,
                                                  const float* __restrict__ bias) {
    extern __shared__ __half smh[];
    __shared__ float bias_s[128];
    const int NC = K / 32;

    int e = g_tile_e[blockIdx.y];
    if (e < 0) return;
    int m0 = g_tile_m[blockIdx.y];
    int mEnd = g_off[e + 1];
    int n0 = blockIdx.x * 128;

    int tid = threadIdx.x, lane = tid & 31, wid = tid >> 5;
    int mw = (wid >> 1) * 64;        // 2 warps in m
    int nw = (wid & 1) * 64;         // 2 warps in n, 64 wide

    bias_s[tid] = bias[e * NTOT + n0 + tid];

    // ---- loader: brow = tid>>3 (0..15), bc4 = tid&7; rows brow + 16*i (i=0..7)
    int brow = tid >> 3, bc4 = tid & 7;
    int sOffBase = brow * TS + bc4 * 4;            // halfs; +i*16*TS per row group

    const float* bBase = W + (size_t)e * NTOT * K + (size_t)(n0 + brow) * K + bc4 * 4;
    // B row stride between groups: 16 * K floats (compile-time).

    const float* aPf[8];       // MODE 0: 8 gathered row pointers
    const __half* aBaseH = nullptr;  // MODE 1: contiguous rows in g_h
    if (MODE == 0) {
        #pragma unroll
        for (int i = 0; i < 8; ++i) {
            int gRow = m0 + brow + 16 * i;
            int cRow = (gRow < mEnd) ? gRow : m0;
            int pair = g_perm[cRow];
            aPf[i] = Ap + (size_t)(pair >> 1) * K + bc4 * 4;
        }
    } else {
        int gRow = m0 + brow;
        int cRow = (gRow < mEnd) ? gRow : m0;  // rows brow+16i all < mEnd or clamp per i
        aBaseH = g_h + (size_t)cRow * K + bc4 * 4 * 2;  // note: bc4*8 halfs? see below
    }
    // MODE 1 A loader uses different mapping: 32 halfs/row = 4 uint4; assign
    // arow = tid>>2 (0..31), aseg = (tid&3)*8; rows arow + 32*i (i=0..3)
    int arow = tid >> 2, aseg = (tid & 3) * 8;
    const __half* aPh[4];
    int aOffH[4];
    if (MODE == 1) {
        #pragma unroll
        for (int i = 0; i < 4; ++i) {
            int gRow = m0 + arow + 32 * i;
            int cRow = (gRow < mEnd) ? gRow : m0;
            aPh[i] = g_h + (size_t)cRow * K + aseg;
            aOffH[i] = (arow + 32 * i) * TS + aseg;
        }
    }

    // ---- fragment addressing
    uint32_t sb = (uint32_t)__cvta_generic_to_shared(smh);
    uint32_t aAddrBase = sb + (uint32_t)(((mw + (lane & 15)) * TS + (lane >> 4) * 8) * 2);
    int bg = lane >> 3;
    int nblk = bg >> 1, khalf = bg & 1;
    uint32_t bAddrBase = sb + (uint32_t)((ABUF_H +
        (nw + nblk * 8 + (lane & 7)) * TS + khalf * 8) * 2);

    float acc[4][8][4];
    #pragma unroll
    for (int mi = 0; mi < 4; ++mi)
        #pragma unroll
        for (int ni = 0; ni < 8; ++ni)
            #pragma unroll
            for (int j = 0; j < 4; ++j) acc[mi][ni][j] = 0.f;

    uint2 hb[8];     // B converted prefetch (8 row-groups)
    uint2 ha[8];     // MODE 0 A converted prefetch
    uint4 qa[4];     // MODE 1 A raw fp16 prefetch

    // ---- fetch chunk 0
    #pragma unroll
    for (int i = 0; i < 8; ++i) hb[i] = cvt2h(*(const float4*)(bBase + (size_t)i * 16 * K));
    if (MODE == 0) {
        #pragma unroll
        for (int i = 0; i < 8; ++i) ha[i] = cvt2h(*(const float4*)(aPf[i]));
    } else {
        #pragma unroll
        for (int i = 0; i < 4; ++i) qa[i] = *(const uint4*)(aPh[i]);
    }
    // ---- store chunk 0 -> buffer 0
    {
        __half* sA = smh;
        __half* sB = smh + ABUF_H;
        #pragma unroll
        for (int i = 0; i < 8; ++i) *(uint2*)(sB + sOffBase + i * 16 * TS) = hb[i];
        if (MODE == 0) {
            #pragma unroll
            for (int i = 0; i < 8; ++i) *(uint2*)(sA + sOffBase + i * 16 * TS) = ha[i];
        } else {
            #pragma unroll
            for (int i = 0; i < 4; ++i) *(uint4*)(sA + aOffH[i]) = qa[i];
        }
    }
    __syncthreads();

    for (int s = 0; s < NC; ++s) {
        int b = s & 1;
        if (s + 1 < NC) {
            #pragma unroll
            for (int i = 0; i < 8; ++i)
                hb[i] = cvt2h(*(const float4*)(bBase + (size_t)i * 16 * K + (s + 1) * 32));
            if (MODE == 0) {
                #pragma unroll
                for (int i = 0; i < 8; ++i)
                    ha[i] = cvt2h(*(const float4*)(aPf[i] + (s + 1) * 32));
            } else {
                #pragma unroll
                for (int i = 0; i < 4; ++i) qa[i] = *(const uint4*)(aPh[i] + (s + 1) * 32);
            }
        }
        // ---- compute on buffer b
        uint32_t aA = aAddrBase + (uint32_t)(b * STAGE_H * 2);
        uint32_t bA = bAddrBase + (uint32_t)(b * STAGE_H * 2);
        #pragma unroll
        for (int ks = 0; ks < 2; ++ks) {
            uint32_t af[4][4];
            #pragma unroll
            for (int mi = 0; mi < 4; ++mi)
                ldsm4(aA + mi * (16 * TS * 2) + ks * 32, af[mi]);
            uint32_t bfr[16];
            #pragma unroll
            for (int ni2 = 0; ni2 < 4; ++ni2)
                ldsm4(bA + ni2 * (16 * TS * 2) + ks * 32, &bfr[ni2 * 4]);
            #pragma unroll
            for (int mi = 0; mi < 4; ++mi)
                #pragma unroll
                for (int ni = 0; ni < 8; ++ni)
                    mma_f16(acc[mi][ni], af[mi], &bfr[ni * 2]);
        }
        if (s + 1 < NC) {
            int nb = b ^ 1;
            __half* sA = smh + nb * STAGE_H;
            __half* sB = sA + ABUF_H;
            #pragma unroll
            for (int i = 0; i < 8; ++i) *(uint2*)(sB + sOffBase + i * 16 * TS) = hb[i];
            if (MODE == 0) {
                #pragma unroll
                for (int i = 0; i < 8; ++i) *(uint2*)(sA + sOffBase + i * 16 * TS) = ha[i];
            } else {
                #pragma unroll
                for (int i = 0; i < 4; ++i) *(uint4*)(sA + aOffH[i]) = qa[i];
            }
            __syncthreads();
        }
    }

    // ---- epilogue
    int r4 = lane >> 2, cc = (lane & 3) * 2;
    #pragma unroll
    for (int mi = 0; mi < 4; ++mi) {
        int row0 = m0 + mw + mi * 16 + r4;
        int row1 = row0 + 8;
        bool v0 = row0 < mEnd, v1 = row1 < mEnd;
        if (MODE == 0) {
            __half* C0 = g_h + (size_t)row0 * NTOT + n0;
            __half* C1 = g_h + (size_t)row1 * NTOT + n0;
            #pragma unroll
            for (int ni = 0; ni < 8; ++ni) {
                int col = nw + ni * 8 + cc;
                float bb0 = bias_s[col], bb1 = bias_s[col + 1];
                const float* d = acc[mi][ni];
                if (v0) {
                    __half2 h = __floats2half2_rn(fmaxf(d[0] + bb0, 0.f),
                                                  fmaxf(d[1] + bb1, 0.f));
                    *(__half2*)&C0[col] = h;
                }
                if (v1) {
                    __half2 h = __floats2half2_rn(fmaxf(d[2] + bb0, 0.f),
                                                  fmaxf(d[3] + bb1, 0.f));
                    *(__half2*)&C1[col] = h;
                }
            }
        } else {
            float w0 = 1.f, w1 = 1.f;
            if (v0) w0 = g_tw[g_perm[row0]];
            if (v1) w1 = g_tw[g_perm[row1]];
            float* C0 = g_contrib + (size_t)row0 * NTOT + n0;
            float* C1 = g_contrib + (size_t)row1 * NTOT + n0;
            #pragma unroll
            for (int ni = 0; ni < 8; ++ni) {
                int col = nw + ni * 8 + cc;
                float bb0 = bias_s[col], bb1 = bias_s[col + 1];
                const float* d = acc[mi][ni];
                if (v0) {
                    float2 o; o.x = (d[0] + bb0) * w0; o.y = (d[1] + bb1) * w0;
                    *(float2*)&C0[col] = o;
                }
                if (v1) {
                    float2 o; o.x = (d[2] + bb0) * w1; o.y = (d[3] + bb1) * w1;
                    *(float2*)&C1[col] = o;
                }
            }
        }
    }
}

// ---------------- combine ----------------------------------------------------
__global__ __launch_bounds__(256) void combine_kernel(float* __restrict__ out) {
    int idx = blockIdx.x * 256 + threadIdx.x;
    int tok = idx >> 8;
    int d4 = idx & 255;
    const float4* c0 = (const float4*)&g_contrib[(size_t)g_inv[tok * 2 + 0] * DOUT];
    const float4* c1 = (const float4*)&g_contrib[(size_t)g_inv[tok * 2 + 1] * DOUT];
    float4 a = c0[d4], b = c1[d4];
    float4 r;
    r.x = a.x + b.x; r.y = a.y + b.y; r.z = a.z + b.z; r.w = a.w + b.w;
    ((float4*)out)[idx] = r;
}

// ---------------- launch -----------------------------------------------------
extern "C" void kernel_launch(void* const* d_in, const int* in_sizes, int n_in,
                              void* d_out, int out_size) {
    const float* x  = (const float*)d_in[0];
    const float* gw = (const float*)d_in[1];
    const float* w1 = (const float*)d_in[2];
    const float* b1 = (const float*)d_in[3];
    const float* w2 = (const float*)d_in[4];
    const float* b2 = (const float*)d_in[5];
    float* out = (float*)d_out;

    cudaFuncSetAttribute(gemm_tc<DI, DH, 0>,
                         cudaFuncAttributeMaxDynamicSharedMemorySize, GEMM_SMEM);
    cudaFuncSetAttribute(gemm_tc<DH, DOUT, 1>,
                         cudaFuncAttributeMaxDynamicSharedMemorySize, GEMM_SMEM);

    init_kernel<<<1, 32>>>();
    gate_kernel<<<NB / 4, 128>>>(x, gw);
    prefix_kernel<<<1, 32>>>();
    scatter_kernel<<<NB / 256, 256>>>();
    gemm_tc<DI, DH, 0><<<dim3(DH / 128, MAXT), 128, GEMM_SMEM>>>(x, w1, b1);
    gemm_tc<DH, DOUT, 1><<<dim3(DOUT / 128, MAXT), 128, GEMM_SMEM>>>(nullptr, w2, b2);
    combine_kernel<<<NB * (DOUT / 4) / 256, 256>>>(out);
}

// round 11
// speedup vs baseline: 1.5913x; 1.1117x over previous
#include <cuda_runtime.h>
#include <cuda_fp16.h>
#include <math.h>
#include <stdint.h>

#define NB   4096
#define NE   16
#define DI   1024
#define DH   2048
#define DOUT 1024
#define NSLOT (NB * 2)
#define MAXT 80          // max 128-row m-tiles across experts (<=79, pad 80)

// ---------------- scratch ----------------------------------------------------
__device__ __half g_h[(size_t)NSLOT * DH];         // fp16 hidden activations
__device__ int    g_perm[NSLOT];
__device__ int    g_counts[NE];
__device__ int    g_cursor[NE];
__device__ int    g_off[NE + 1];
__device__ int    g_tidx[NB * 2];
__device__ float  g_tw[NB * 2];
__device__ int    g_tile_e[MAXT];
__device__ int    g_tile_m[MAXT];

// ---------------- helpers ----------------------------------------------------
__device__ __forceinline__ void ldsm4(uint32_t addr, uint32_t* a) {
    asm volatile("ldmatrix.sync.aligned.m8n8.x4.shared.b16 {%0,%1,%2,%3}, [%4];"
                 : "=r"(a[0]), "=r"(a[1]), "=r"(a[2]), "=r"(a[3]) : "r"(addr));
}
__device__ __forceinline__ void mma_f16(float* d, const uint32_t* a, const uint32_t* b) {
    asm volatile(
        "mma.sync.aligned.m16n8k16.row.col.f32.f16.f16.f32 "
        "{%0,%1,%2,%3}, {%4,%5,%6,%7}, {%8,%9}, {%0,%1,%2,%3};"
        : "+f"(d[0]), "+f"(d[1]), "+f"(d[2]), "+f"(d[3])
        : "r"(a[0]), "r"(a[1]), "r"(a[2]), "r"(a[3]), "r"(b[0]), "r"(b[1]));
}
__device__ __forceinline__ uint32_t h2bits(__half2 h) {
    return *reinterpret_cast<uint32_t*>(&h);
}
__device__ __forceinline__ uint2 cvt2h(float4 v) {
    uint2 u;
    u.x = h2bits(__floats2half2_rn(v.x, v.y));
    u.y = h2bits(__floats2half2_rn(v.z, v.w));
    return u;
}
// vector reduction: out[0] += a, out[1] += b (single 8B transaction)
__device__ __forceinline__ void red2(float* p, float a, float b) {
    asm volatile("red.global.add.v2.f32 [%0], {%1, %2};"
                 :: "l"(p), "f"(a), "f"(b) : "memory");
}

// ---------------- zero out + reset counters (runs first every replay) --------
__global__ __launch_bounds__(256) void zero_kernel(float* __restrict__ out) {
    int idx = blockIdx.x * 256 + threadIdx.x;
    ((float4*)out)[idx] = make_float4(0.f, 0.f, 0.f, 0.f);
    if (blockIdx.x == 0 && threadIdx.x < NE) {
        g_counts[threadIdx.x] = 0;
        g_cursor[threadIdx.x] = 0;
    }
}

// ---------------- gate (fp32 exact — routing must match reference) -----------
__global__ __launch_bounds__(128) void gate_kernel(const float* __restrict__ x,
                                                   const float* __restrict__ gw) {
    __shared__ float xs[4][DI];
    __shared__ float sc[4][NE];
    int t0 = blockIdx.x * 4;

    const float4* xsrc = (const float4*)(x + (size_t)t0 * DI);
    float4* xd = (float4*)&xs[0][0];
    #pragma unroll 4
    for (int i = threadIdx.x; i < 4 * DI / 4; i += 128) xd[i] = xsrc[i];
    __syncthreads();

    int warp = threadIdx.x >> 5, lane = threadIdx.x & 31;
    for (int e = warp * 4; e < warp * 4 + 4; ++e) {
        float s0 = 0.f, s1 = 0.f, s2 = 0.f, s3 = 0.f;
        for (int i = lane; i < DI; i += 32) {
            float g = gw[e * DI + i];
            s0 += xs[0][i] * g; s1 += xs[1][i] * g;
            s2 += xs[2][i] * g; s3 += xs[3][i] * g;
        }
        #pragma unroll
        for (int o = 16; o > 0; o >>= 1) {
            s0 += __shfl_xor_sync(0xffffffffu, s0, o);
            s1 += __shfl_xor_sync(0xffffffffu, s1, o);
            s2 += __shfl_xor_sync(0xffffffffu, s2, o);
            s3 += __shfl_xor_sync(0xffffffffu, s3, o);
        }
        if (lane == 0) { sc[0][e] = s0; sc[1][e] = s1; sc[2][e] = s2; sc[3][e] = s3; }
    }
    __syncthreads();

    if (threadIdx.x < 4) {
        int tt = threadIdx.x;
        int tok = t0 + tt;
        float bv = -1e30f; int bi = 0;
        #pragma unroll
        for (int e = 0; e < NE; ++e) {
            float v = sc[tt][e];
            if (v > bv) { bv = v; bi = e; }
        }
        float bv2 = -1e30f; int bi2 = 0;
        #pragma unroll
        for (int e = 0; e < NE; ++e) {
            if (e == bi) continue;
            float v = sc[tt][e];
            if (v > bv2) { bv2 = v; bi2 = e; }
        }
        float e2 = expf(bv2 - bv);
        float inv = 1.0f / (1.0f + e2);
        g_tidx[tok * 2 + 0] = bi;  g_tw[tok * 2 + 0] = inv;
        g_tidx[tok * 2 + 1] = bi2; g_tw[tok * 2 + 1] = e2 * inv;
        atomicAdd(&g_counts[bi], 1);
        atomicAdd(&g_counts[bi2], 1);
    }
}

// ---------------- prefix + exact tile table ----------------------------------
__global__ void prefix_kernel() {
    if (threadIdx.x == 0) {
        int s = 0;
        #pragma unroll
        for (int e = 0; e < NE; ++e) { g_off[e] = s; s += g_counts[e]; }
        g_off[NE] = s;
        int nt = 0;
        for (int e = 0; e < NE; ++e)
            for (int m = g_off[e]; m < g_off[e + 1]; m += 128) {
                g_tile_e[nt] = e; g_tile_m[nt] = m; ++nt;
            }
        for (; nt < MAXT; ++nt) g_tile_e[nt] = -1;
    }
}

// ---------------- scatter (two-level, low contention) -------------------------
__global__ __launch_bounds__(256) void scatter_kernel() {
    __shared__ int lcnt[NE];
    __shared__ int lbase[NE];
    int tid = threadIdx.x;
    int tok = blockIdx.x * 256 + tid;
    if (tid < NE) lcnt[tid] = 0;
    __syncthreads();
    int e0 = g_tidx[tok * 2 + 0], e1 = g_tidx[tok * 2 + 1];
    int r0 = atomicAdd(&lcnt[e0], 1);
    int r1 = atomicAdd(&lcnt[e1], 1);
    __syncthreads();
    if (tid < NE) lbase[tid] = atomicAdd(&g_cursor[tid], lcnt[tid]);
    __syncthreads();
    g_perm[g_off[e0] + lbase[e0] + r0] = tok * 2 + 0;
    g_perm[g_off[e1] + lbase[e1] + r1] = tok * 2 + 1;
}

// ---------------- fp16 mma.sync grouped GEMM (R6 core, frozen) ----------------
// CTA tile 128x128, BK=32, double-buffered 40KB, 2 CTA/SM, 256 threads,
// 8 warps (2m x 4n), warp tile 64x32. Grid: x = m-tile index (B-tile L2 reuse
// across consecutive CTAs of the same expert), y = n-tile.
// MODE 0: g_h = relu(gather(x) @ w1^T + b1)        (K=DI,  NTOT=DH, A fp32)
// MODE 1: red.add(out, (g_h @ w2^T + b2) * gate_w) (K=DH,  NTOT=DOUT, A fp16)
#define TS 40
#define ABUF_H (128 * TS)
#define STAGE_H (2 * ABUF_H)
#define GEMM_SMEM (2 * STAGE_H * 2)   // 40960 bytes

template <int K, int NTOT, int MODE>
__global__ __launch_bounds__(256) void gemm_tc(const float* __restrict__ Ap,
                                               const float* __restrict__ W,
                                               const float* __restrict__ bias,
                                               float* __restrict__ out) {
    extern __shared__ __half smh[];
    __shared__ float bias_s[128];
    const int NC = K / 32;

    int e = g_tile_e[blockIdx.x];
    if (e < 0) return;
    int m0 = g_tile_m[blockIdx.x];
    int mEnd = g_off[e + 1];
    int n0 = blockIdx.y * 128;

    int tid = threadIdx.x, lane = tid & 31, wid = tid >> 5;
    int mw = (wid >> 2) * 64;
    int nw = (wid & 3) * 32;

    if (tid < 128) bias_s[tid] = bias[e * NTOT + n0 + tid];

    // ---- B loader: row = tid>>3 + 32*i, c4 = tid&7
    int brow = tid >> 3, bc4 = tid & 7;
    const float* bP[4];
    int bOff[4];
    #pragma unroll
    for (int i = 0; i < 4; ++i) {
        int row = brow + 32 * i;
        bP[i] = W + (size_t)e * NTOT * K + (size_t)(n0 + row) * K + bc4 * 4;
        bOff[i] = row * TS + bc4 * 4;
    }

    // ---- A loader
    const float* aP[4];
    const __half* aPh[2];
    int aOff[4], aOffH[2];
    if (MODE == 0) {
        #pragma unroll
        for (int i = 0; i < 4; ++i) {
            int row = brow + 32 * i;
            int gRow = m0 + row;
            int cRow = (gRow < mEnd) ? gRow : m0;
            int pair = g_perm[cRow];
            aP[i] = Ap + (size_t)(pair >> 1) * K + bc4 * 4;
            aOff[i] = row * TS + bc4 * 4;
        }
    } else {
        int arow = tid >> 2, aseg = tid & 3;
        #pragma unroll
        for (int i = 0; i < 2; ++i) {
            int row = arow + 64 * i;
            int gRow = m0 + row;
            int cRow = (gRow < mEnd) ? gRow : m0;
            aPh[i] = g_h + (size_t)cRow * K + aseg * 8;
            aOffH[i] = row * TS + aseg * 8;
        }
    }

    // ---- fragment addressing
    uint32_t sb = (uint32_t)__cvta_generic_to_shared(smh);
    uint32_t aAddrBase = sb + (uint32_t)(((mw + (lane & 15)) * TS + (lane >> 4) * 8) * 2);
    int bg = lane >> 3;
    int nblk = bg >> 1, khalf = bg & 1;
    uint32_t bAddrBase = sb + (uint32_t)((ABUF_H +
        (nw + nblk * 8 + (lane & 7)) * TS + khalf * 8) * 2);

    float acc[4][4][4];
    #pragma unroll
    for (int mi = 0; mi < 4; ++mi)
        #pragma unroll
        for (int ni = 0; ni < 4; ++ni)
            #pragma unroll
            for (int j = 0; j < 4; ++j) acc[mi][ni][j] = 0.f;

    float4 pb[4];
    float4 pa[4];
    uint4 qa[2];

    // ---- fetch + store chunk 0
    #pragma unroll
    for (int i = 0; i < 4; ++i) pb[i] = *(const float4*)(bP[i]);
    if (MODE == 0) {
        #pragma unroll
        for (int i = 0; i < 4; ++i) pa[i] = *(const float4*)(aP[i]);
    } else {
        #pragma unroll
        for (int i = 0; i < 2; ++i) qa[i] = *(const uint4*)(aPh[i]);
    }
    {
        __half* sA = smh;
        __half* sB = smh + ABUF_H;
        #pragma unroll
        for (int i = 0; i < 4; ++i) {
            uint2 u = cvt2h(pb[i]);
            *(uint2*)(sB + bOff[i]) = u;
        }
        if (MODE == 0) {
            #pragma unroll
            for (int i = 0; i < 4; ++i) {
                uint2 u = cvt2h(pa[i]);
                *(uint2*)(sA + aOff[i]) = u;
            }
        } else {
            #pragma unroll
            for (int i = 0; i < 2; ++i) *(uint4*)(sA + aOffH[i]) = qa[i];
        }
    }
    __syncthreads();

    for (int s = 0; s < NC; ++s) {
        int b = s & 1;
        if (s + 1 < NC) {
            #pragma unroll
            for (int i = 0; i < 4; ++i) pb[i] = *(const float4*)(bP[i] + (s + 1) * 32);
            if (MODE == 0) {
                #pragma unroll
                for (int i = 0; i < 4; ++i) pa[i] = *(const float4*)(aP[i] + (s + 1) * 32);
            } else {
                #pragma unroll
                for (int i = 0; i < 2; ++i) qa[i] = *(const uint4*)(aPh[i] + (s + 1) * 32);
            }
        }
        // ---- compute on buffer b
        uint32_t aA = aAddrBase + (uint32_t)(b * STAGE_H * 2);
        uint32_t bA = bAddrBase + (uint32_t)(b * STAGE_H * 2);
        #pragma unroll
        for (int ks = 0; ks < 2; ++ks) {
            uint32_t af[4][4];
            #pragma unroll
            for (int mi = 0; mi < 4; ++mi)
                ldsm4(aA + mi * (16 * TS * 2) + ks * 32, af[mi]);
            uint32_t bfr[8];
            #pragma unroll
            for (int ni2 = 0; ni2 < 2; ++ni2)
                ldsm4(bA + ni2 * (16 * TS * 2) + ks * 32, &bfr[ni2 * 4]);
            #pragma unroll
            for (int mi = 0; mi < 4; ++mi)
                #pragma unroll
                for (int ni = 0; ni < 4; ++ni)
                    mma_f16(acc[mi][ni], af[mi], &bfr[ni * 2]);
        }
        if (s + 1 < NC) {
            int nb = b ^ 1;
            __half* sA = smh + nb * STAGE_H;
            __half* sB = sA + ABUF_H;
            #pragma unroll
            for (int i = 0; i < 4; ++i) {
                uint2 u = cvt2h(pb[i]);
                *(uint2*)(sB + bOff[i]) = u;
            }
            if (MODE == 0) {
                #pragma unroll
                for (int i = 0; i < 4; ++i) {
                    uint2 u = cvt2h(pa[i]);
                    *(uint2*)(sA + aOff[i]) = u;
                }
            } else {
                #pragma unroll
                for (int i = 0; i < 2; ++i) *(uint4*)(sA + aOffH[i]) = qa[i];
            }
            __syncthreads();
        }
    }

    // ---- epilogue
    int r4 = lane >> 2, cc = (lane & 3) * 2;
    #pragma unroll
    for (int mi = 0; mi < 4; ++mi) {
        int row0 = m0 + mw + mi * 16 + r4;
        int row1 = row0 + 8;
        bool v0 = row0 < mEnd, v1 = row1 < mEnd;
        if (MODE == 0) {
            __half* C0 = g_h + (size_t)row0 * NTOT + n0;
            __half* C1 = g_h + (size_t)row1 * NTOT + n0;
            #pragma unroll
            for (int ni = 0; ni < 4; ++ni) {
                int col = nw + ni * 8 + cc;
                float bb0 = bias_s[col], bb1 = bias_s[col + 1];
                const float* d = acc[mi][ni];
                if (v0) {
                    __half2 h = __floats2half2_rn(fmaxf(d[0] + bb0, 0.f),
                                                  fmaxf(d[1] + bb1, 0.f));
                    *(__half2*)&C0[col] = h;
                }
                if (v1) {
                    __half2 h = __floats2half2_rn(fmaxf(d[2] + bb0, 0.f),
                                                  fmaxf(d[3] + bb1, 0.f));
                    *(__half2*)&C1[col] = h;
                }
            }
        } else {
            int p0 = 0, p1 = 0;
            float w0 = 0.f, w1 = 0.f;
            if (v0) { p0 = g_perm[row0]; w0 = g_tw[p0]; }
            if (v1) { p1 = g_perm[row1]; w1 = g_tw[p1]; }
            float* O0 = out + (size_t)(p0 >> 1) * DOUT + n0;
            float* O1 = out + (size_t)(p1 >> 1) * DOUT + n0;
            #pragma unroll
            for (int ni = 0; ni < 4; ++ni) {
                int col = nw + ni * 8 + cc;
                float bb0 = bias_s[col], bb1 = bias_s[col + 1];
                const float* d = acc[mi][ni];
                if (v0) red2(O0 + col, (d[0] + bb0) * w0, (d[1] + bb1) * w0);
                if (v1) red2(O1 + col, (d[2] + bb0) * w1, (d[3] + bb1) * w1);
            }
        }
    }
}

// ---------------- launch -----------------------------------------------------
extern "C" void kernel_launch(void* const* d_in, const int* in_sizes, int n_in,
                              void* d_out, int out_size) {
    const float* x  = (const float*)d_in[0];
    const float* gw = (const float*)d_in[1];
    const float* w1 = (const float*)d_in[2];
    const float* b1 = (const float*)d_in[3];
    const float* w2 = (const float*)d_in[4];
    const float* b2 = (const float*)d_in[5];
    float* out = (float*)d_out;

    cudaFuncSetAttribute(gemm_tc<DI, DH, 0>,
                         cudaFuncAttributeMaxDynamicSharedMemorySize, GEMM_SMEM);
    cudaFuncSetAttribute(gemm_tc<DH, DOUT, 1>,
                         cudaFuncAttributeMaxDynamicSharedMemorySize, GEMM_SMEM);

    zero_kernel<<<NB * DOUT / 4 / 256, 256>>>(out);
    gate_kernel<<<NB / 4, 128>>>(x, gw);
    prefix_kernel<<<1, 32>>>();
    scatter_kernel<<<NB / 256, 256>>>();
    gemm_tc<DI, DH, 0><<<dim3(MAXT, DH / 128), 256, GEMM_SMEM>>>(x, w1, b1, nullptr);
    gemm_tc<DH, DOUT, 1><<<dim3(MAXT, DOUT / 128), 256, GEMM_SMEM>>>(nullptr, w2, b2, out);
}

// round 12
// speedup vs baseline: 1.6157x; 1.0153x over previous
#include <cuda_runtime.h>
#include <cuda_fp16.h>
#include <math.h>
#include <stdint.h>

#define NB   4096
#define NE   16
#define DI   1024
#define DH   2048
#define DOUT 1024
#define NSLOT (NB * 2)
#define MAXT 80            // max 128-row m-tiles across experts (<=79, pad 80)
#define NT1  (DH / 128)    // 16 n-tiles in GEMM1
#define NT2  (DOUT / 128)  // 8 n-tiles in GEMM2
#define T1TOT (MAXT * NT1) // 1280
#define TTOT  (MAXT * (NT1 + NT2))
#define NCTA  296          // 2 CTAs per SM x 148 SMs

// ---------------- scratch ----------------------------------------------------
__device__ __half g_h[(size_t)NSLOT * DH];
__device__ int    g_perm[NSLOT];
__device__ int    g_counts[NE];
__device__ int    g_cursor[NE];
__device__ int    g_off[NE + 1];
__device__ int    g_tidx[NB * 2];
__device__ float  g_tw[NB * 2];
__device__ int    g_tile_e[MAXT];
__device__ int    g_tile_m[MAXT];
__device__ int    g_done[MAXT];
__device__ int    g_ticket;
__device__ int    g_gatefin;

// ---------------- helpers ----------------------------------------------------
__device__ __forceinline__ void ldsm4(uint32_t addr, uint32_t* a) {
    asm volatile("ldmatrix.sync.aligned.m8n8.x4.shared.b16 {%0,%1,%2,%3}, [%4];"
                 : "=r"(a[0]), "=r"(a[1]), "=r"(a[2]), "=r"(a[3]) : "r"(addr));
}
__device__ __forceinline__ void mma_f16(float* d, const uint32_t* a, const uint32_t* b) {
    asm volatile(
        "mma.sync.aligned.m16n8k16.row.col.f32.f16.f16.f32 "
        "{%0,%1,%2,%3}, {%4,%5,%6,%7}, {%8,%9}, {%0,%1,%2,%3};"
        : "+f"(d[0]), "+f"(d[1]), "+f"(d[2]), "+f"(d[3])
        : "r"(a[0]), "r"(a[1]), "r"(a[2]), "r"(a[3]), "r"(b[0]), "r"(b[1]));
}
__device__ __forceinline__ uint32_t h2bits(__half2 h) {
    return *reinterpret_cast<uint32_t*>(&h);
}
__device__ __forceinline__ uint2 cvt2h(float4 v) {
    uint2 u;
    u.x = h2bits(__floats2half2_rn(v.x, v.y));
    u.y = h2bits(__floats2half2_rn(v.z, v.w));
    return u;
}
__device__ __forceinline__ void red2(float* p, float a, float b) {
    asm volatile("red.global.add.v2.f32 [%0], {%1, %2};"
                 :: "l"(p), "f"(a), "f"(b) : "memory");
}

// ---------------- zero out + reset all control state --------------------------
__global__ __launch_bounds__(256) void zero_kernel(float* __restrict__ out) {
    int idx = blockIdx.x * 256 + threadIdx.x;
    ((float4*)out)[idx] = make_float4(0.f, 0.f, 0.f, 0.f);
    if (blockIdx.x == 0) {
        if (threadIdx.x < NE) { g_counts[threadIdx.x] = 0; g_cursor[threadIdx.x] = 0; }
        if (threadIdx.x < MAXT) g_done[threadIdx.x] = 0;
        if (threadIdx.x == 0) { g_ticket = 0; g_gatefin = 0; }
    }
}

// ---------------- gate (fp32 exact) + last-block prefix/tile-table ------------
__global__ __launch_bounds__(128) void gate_kernel(const float* __restrict__ x,
                                                   const float* __restrict__ gw) {
    __shared__ float xs[4][DI];
    __shared__ float sc[4][NE];
    __shared__ int s_last;
    int t0 = blockIdx.x * 4;

    const float4* xsrc = (const float4*)(x + (size_t)t0 * DI);
    float4* xd = (float4*)&xs[0][0];
    #pragma unroll 4
    for (int i = threadIdx.x; i < 4 * DI / 4; i += 128) xd[i] = xsrc[i];
    __syncthreads();

    int warp = threadIdx.x >> 5, lane = threadIdx.x & 31;
    for (int e = warp * 4; e < warp * 4 + 4; ++e) {
        float s0 = 0.f, s1 = 0.f, s2 = 0.f, s3 = 0.f;
        for (int i = lane; i < DI; i += 32) {
            float g = gw[e * DI + i];
            s0 += xs[0][i] * g; s1 += xs[1][i] * g;
            s2 += xs[2][i] * g; s3 += xs[3][i] * g;
        }
        #pragma unroll
        for (int o = 16; o > 0; o >>= 1) {
            s0 += __shfl_xor_sync(0xffffffffu, s0, o);
            s1 += __shfl_xor_sync(0xffffffffu, s1, o);
            s2 += __shfl_xor_sync(0xffffffffu, s2, o);
            s3 += __shfl_xor_sync(0xffffffffu, s3, o);
        }
        if (lane == 0) { sc[0][e] = s0; sc[1][e] = s1; sc[2][e] = s2; sc[3][e] = s3; }
    }
    __syncthreads();

    if (threadIdx.x < 4) {
        int tt = threadIdx.x;
        int tok = t0 + tt;
        float bv = -1e30f; int bi = 0;
        #pragma unroll
        for (int e = 0; e < NE; ++e) {
            float v = sc[tt][e];
            if (v > bv) { bv = v; bi = e; }
        }
        float bv2 = -1e30f; int bi2 = 0;
        #pragma unroll
        for (int e = 0; e < NE; ++e) {
            if (e == bi) continue;
            float v = sc[tt][e];
            if (v > bv2) { bv2 = v; bi2 = e; }
        }
        float e2 = expf(bv2 - bv);
        float inv = 1.0f / (1.0f + e2);
        g_tidx[tok * 2 + 0] = bi;  g_tw[tok * 2 + 0] = inv;
        g_tidx[tok * 2 + 1] = bi2; g_tw[tok * 2 + 1] = e2 * inv;
        atomicAdd(&g_counts[bi], 1);
        atomicAdd(&g_counts[bi2], 1);
    }

    // last finished block computes prefix sums + tile table
    __threadfence();
    __syncthreads();
    if (threadIdx.x == 0)
        s_last = (atomicAdd(&g_gatefin, 1) == (int)gridDim.x - 1) ? 1 : 0;
    __syncthreads();
    if (s_last && threadIdx.x == 0) {
        int s = 0;
        #pragma unroll
        for (int e = 0; e < NE; ++e) { g_off[e] = s; s += g_counts[e]; }
        g_off[NE] = s;
        int nt = 0;
        for (int e = 0; e < NE; ++e)
            for (int m = g_off[e]; m < g_off[e + 1]; m += 128) {
                g_tile_e[nt] = e; g_tile_m[nt] = m; ++nt;
            }
        for (; nt < MAXT; ++nt) g_tile_e[nt] = -1;
    }
}

// ---------------- scatter (two-level, low contention) -------------------------
__global__ __launch_bounds__(256) void scatter_kernel() {
    __shared__ int lcnt[NE];
    __shared__ int lbase[NE];
    int tid = threadIdx.x;
    int tok = blockIdx.x * 256 + tid;
    if (tid < NE) lcnt[tid] = 0;
    __syncthreads();
    int e0 = g_tidx[tok * 2 + 0], e1 = g_tidx[tok * 2 + 1];
    int r0 = atomicAdd(&lcnt[e0], 1);
    int r1 = atomicAdd(&lcnt[e1], 1);
    __syncthreads();
    if (tid < NE) lbase[tid] = atomicAdd(&g_cursor[tid], lcnt[tid]);
    __syncthreads();
    g_perm[g_off[e0] + lbase[e0] + r0] = tok * 2 + 0;
    g_perm[g_off[e1] + lbase[e1] + r1] = tok * 2 + 1;
}

// ---------------- GEMM tile body (R6/R11 core, frozen) ------------------------
#define TS 40
#define ABUF_H (128 * TS)
#define STAGE_H (2 * ABUF_H)
#define GEMM_SMEM (2 * STAGE_H * 2)   // 40960 bytes

template <int K, int NTOT, int MODE>
__device__ __forceinline__ void process_tile(
    __half* smh, float* bias_s,
    int e, int m0, int mEnd, int n0,
    const float* __restrict__ Ap, const float* __restrict__ W,
    const float* __restrict__ bias, float* __restrict__ out)
{
    const int NC = K / 32;
    int tid = threadIdx.x, lane = tid & 31, wid = tid >> 5;
    int mw = (wid >> 2) * 64;
    int nw = (wid & 3) * 32;

    if (tid < 128) bias_s[tid] = bias[e * NTOT + n0 + tid];

    int brow = tid >> 3, bc4 = tid & 7;
    const float* bP[4];
    int bOff[4];
    #pragma unroll
    for (int i = 0; i < 4; ++i) {
        int row = brow + 32 * i;
        bP[i] = W + (size_t)e * NTOT * K + (size_t)(n0 + row) * K + bc4 * 4;
        bOff[i] = row * TS + bc4 * 4;
    }

    const float* aP[4];
    const __half* aPh[2];
    int aOff[4], aOffH[2];
    if (MODE == 0) {
        #pragma unroll
        for (int i = 0; i < 4; ++i) {
            int row = brow + 32 * i;
            int gRow = m0 + row;
            int cRow = (gRow < mEnd) ? gRow : m0;
            int pair = g_perm[cRow];
            aP[i] = Ap + (size_t)(pair >> 1) * K + bc4 * 4;
            aOff[i] = row * TS + bc4 * 4;
        }
    } else {
        int arow = tid >> 2, aseg = tid & 3;
        #pragma unroll
        for (int i = 0; i < 2; ++i) {
            int row = arow + 64 * i;
            int gRow = m0 + row;
            int cRow = (gRow < mEnd) ? gRow : m0;
            aPh[i] = g_h + (size_t)cRow * K + aseg * 8;
            aOffH[i] = row * TS + aseg * 8;
        }
    }

    uint32_t sb = (uint32_t)__cvta_generic_to_shared(smh);
    uint32_t aAddrBase = sb + (uint32_t)(((mw + (lane & 15)) * TS + (lane >> 4) * 8) * 2);
    int bg = lane >> 3;
    int nblk = bg >> 1, khalf = bg & 1;
    uint32_t bAddrBase = sb + (uint32_t)((ABUF_H +
        (nw + nblk * 8 + (lane & 7)) * TS + khalf * 8) * 2);

    float acc[4][4][4];
    #pragma unroll
    for (int mi = 0; mi < 4; ++mi)
        #pragma unroll
        for (int ni = 0; ni < 4; ++ni)
            #pragma unroll
            for (int j = 0; j < 4; ++j) acc[mi][ni][j] = 0.f;

    float4 pb[4];
    float4 pa[4];
    uint4 qa[2];

    #pragma unroll
    for (int i = 0; i < 4; ++i) pb[i] = *(const float4*)(bP[i]);
    if (MODE == 0) {
        #pragma unroll
        for (int i = 0; i < 4; ++i) pa[i] = *(const float4*)(aP[i]);
    } else {
        #pragma unroll
        for (int i = 0; i < 2; ++i) qa[i] = *(const uint4*)(aPh[i]);
    }
    {
        __half* sA = smh;
        __half* sB = smh + ABUF_H;
        #pragma unroll
        for (int i = 0; i < 4; ++i) {
            uint2 u = cvt2h(pb[i]);
            *(uint2*)(sB + bOff[i]) = u;
        }
        if (MODE == 0) {
            #pragma unroll
            for (int i = 0; i < 4; ++i) {
                uint2 u = cvt2h(pa[i]);
                *(uint2*)(sA + aOff[i]) = u;
            }
        } else {
            #pragma unroll
            for (int i = 0; i < 2; ++i) *(uint4*)(sA + aOffH[i]) = qa[i];
        }
    }
    __syncthreads();

    for (int s = 0; s < NC; ++s) {
        int b = s & 1;
        if (s + 1 < NC) {
            #pragma unroll
            for (int i = 0; i < 4; ++i) pb[i] = *(const float4*)(bP[i] + (s + 1) * 32);
            if (MODE == 0) {
                #pragma unroll
                for (int i = 0; i < 4; ++i) pa[i] = *(const float4*)(aP[i] + (s + 1) * 32);
            } else {
                #pragma unroll
                for (int i = 0; i < 2; ++i) qa[i] = *(const uint4*)(aPh[i] + (s + 1) * 32);
            }
        }
        uint32_t aA = aAddrBase + (uint32_t)(b * STAGE_H * 2);
        uint32_t bA = bAddrBase + (uint32_t)(b * STAGE_H * 2);
        #pragma unroll
        for (int ks = 0; ks < 2; ++ks) {
            uint32_t af[4][4];
            #pragma unroll
            for (int mi = 0; mi < 4; ++mi)
                ldsm4(aA + mi * (16 * TS * 2) + ks * 32, af[mi]);
            uint32_t bfr[8];
            #pragma unroll
            for (int ni2 = 0; ni2 < 2; ++ni2)
                ldsm4(bA + ni2 * (16 * TS * 2) + ks * 32, &bfr[ni2 * 4]);
            #pragma unroll
            for (int mi = 0; mi < 4; ++mi)
                #pragma unroll
                for (int ni = 0; ni < 4; ++ni)
                    mma_f16(acc[mi][ni], af[mi], &bfr[ni * 2]);
        }
        if (s + 1 < NC) {
            int nb = b ^ 1;
            __half* sA = smh + nb * STAGE_H;
            __half* sB = sA + ABUF_H;
            #pragma unroll
            for (int i = 0; i < 4; ++i) {
                uint2 u = cvt2h(pb[i]);
                *(uint2*)(sB + bOff[i]) = u;
            }
            if (MODE == 0) {
                #pragma unroll
                for (int i = 0; i < 4; ++i) {
                    uint2 u = cvt2h(pa[i]);
                    *(uint2*)(sA + aOff[i]) = u;
                }
            } else {
                #pragma unroll
                for (int i = 0; i < 2; ++i) *(uint4*)(sA + aOffH[i]) = qa[i];
            }
            __syncthreads();
        }
    }

    int r4 = lane >> 2, cc = (lane & 3) * 2;
    #pragma unroll
    for (int mi = 0; mi < 4; ++mi) {
        int row0 = m0 + mw + mi * 16 + r4;
        int row1 = row0 + 8;
        bool v0 = row0 < mEnd, v1 = row1 < mEnd;
        if (MODE == 0) {
            __half* C0 = g_h + (size_t)row0 * NTOT + n0;
            __half* C1 = g_h + (size_t)row1 * NTOT + n0;
            #pragma unroll
            for (int ni = 0; ni < 4; ++ni) {
                int col = nw + ni * 8 + cc;
                float bb0 = bias_s[col], bb1 = bias_s[col + 1];
                const float* d = acc[mi][ni];
                if (v0) {
                    __half2 h = __floats2half2_rn(fmaxf(d[0] + bb0, 0.f),
                                                  fmaxf(d[1] + bb1, 0.f));
                    *(__half2*)&C0[col] = h;
                }
                if (v1) {
                    __half2 h = __floats2half2_rn(fmaxf(d[2] + bb0, 0.f),
                                                  fmaxf(d[3] + bb1, 0.f));
                    *(__half2*)&C1[col] = h;
                }
            }
        } else {
            int p0 = 0, p1 = 0;
            float w0 = 0.f, w1 = 0.f;
            if (v0) { p0 = g_perm[row0]; w0 = g_tw[p0]; }
            if (v1) { p1 = g_perm[row1]; w1 = g_tw[p1]; }
            float* O0 = out + (size_t)(p0 >> 1) * DOUT + n0;
            float* O1 = out + (size_t)(p1 >> 1) * DOUT + n0;
            #pragma unroll
            for (int ni = 0; ni < 4; ++ni) {
                int col = nw + ni * 8 + cc;
                float bb0 = bias_s[col], bb1 = bias_s[col + 1];
                const float* d = acc[mi][ni];
                if (v0) red2(O0 + col, (d[0] + bb0) * w0, (d[1] + bb1) * w0);
                if (v1) red2(O1 + col, (d[2] + bb0) * w1, (d[3] + bb1) * w1);
            }
        }
    }
}

// ---------------- persistent fused GEMM1+GEMM2 --------------------------------
__global__ __launch_bounds__(256, 2) void moe_gemm(const float* __restrict__ x,
                                                   const float* __restrict__ w1,
                                                   const float* __restrict__ b1,
                                                   const float* __restrict__ w2,
                                                   const float* __restrict__ b2,
                                                   float* __restrict__ out) {
    extern __shared__ __half smh[];
    __shared__ float bias_s[128];
    __shared__ int s_t;
    int tid = threadIdx.x;

    for (;;) {
        __syncthreads();                 // smem/bias_s reuse barrier
        if (tid == 0) s_t = atomicAdd(&g_ticket, 1);
        __syncthreads();
        int t = s_t;
        if (t >= TTOT) return;

        if (t < T1TOT) {
            int mt = t / NT1, nt = t % NT1;
            int e = g_tile_e[mt];
            if (e < 0) continue;
            int m0 = g_tile_m[mt];
            int mEnd = g_off[e + 1];
            process_tile<DI, DH, 0>(smh, bias_s, e, m0, mEnd, nt * 128,
                                    x, w1, b1, nullptr);
            __threadfence();             // publish g_h stores
            __syncthreads();
            if (tid == 0) atomicAdd(&g_done[mt], 1);
        } else {
            int idx = t - T1TOT;
            int mt = idx / NT2, nt = idx % NT2;
            int e = g_tile_e[mt];
            if (e < 0) continue;
            if (tid == 0) {
                while (*(volatile int*)&g_done[mt] < NT1) {}
                __threadfence();
            }
            __syncthreads();
            int m0 = g_tile_m[mt];
            int mEnd = g_off[e + 1];
            process_tile<DH, DOUT, 1>(smh, bias_s, e, m0, mEnd, nt * 128,
                                      nullptr, w2, b2, out);
        }
    }
}

// ---------------- launch -----------------------------------------------------
extern "C" void kernel_launch(void* const* d_in, const int* in_sizes, int n_in,
                              void* d_out, int out_size) {
    const float* x  = (const float*)d_in[0];
    const float* gw = (const float*)d_in[1];
    const float* w1 = (const float*)d_in[2];
    const float* b1 = (const float*)d_in[3];
    const float* w2 = (const float*)d_in[4];
    const float* b2 = (const float*)d_in[5];
    float* out = (float*)d_out;

    cudaFuncSetAttribute(moe_gemm,
                         cudaFuncAttributeMaxDynamicSharedMemorySize, GEMM_SMEM);

    zero_kernel<<<NB * DOUT / 4 / 256, 256>>>(out);
    gate_kernel<<<NB / 4, 128>>>(x, gw);
    scatter_kernel<<<NB / 256, 256>>>();
    moe_gemm<<<NCTA, 256, GEMM_SMEM>>>(x, w1, b1, w2, b2, out);
}

// round 13
// speedup vs baseline: 1.6221x; 1.0039x over previous
#include <cuda_runtime.h>
#include <cuda_fp16.h>
#include <math.h>
#include <stdint.h>

#define NB   4096
#define NE   16
#define DI   1024
#define DH   2048
#define DOUT 1024
#define NSLOT (NB * 2)
#define MAXT 80            // max 128-row m-tiles across experts (<=79, pad 80)
#define NT1  (DH / 128)    // 16 n-tiles in GEMM1
#define NT2  (DOUT / 128)  // 8 n-tiles in GEMM2
#define T1TOT (MAXT * NT1) // 1280
#define TTOT  (MAXT * (NT1 + NT2))
#define NCTA  296          // 2 CTAs per SM x 148 SMs
#define ZB   128           // out-zero blocks appended to gate grid

// ---------------- scratch ----------------------------------------------------
__device__ __half g_h[(size_t)NSLOT * DH];
__device__ int    g_perm[NSLOT];
__device__ int    g_counts[NE];
__device__ int    g_cursor[NE];
__device__ int    g_off[NE + 1];
__device__ int    g_tidx[NB * 2];
__device__ float  g_tw[NB * 2];
__device__ int    g_tile_e[MAXT];
__device__ int    g_tile_m[MAXT];
__device__ int    g_done[MAXT];
__device__ int    g_ticket;
__device__ int    g_gatefin;
__device__ int    g_finish;

// ---------------- helpers ----------------------------------------------------
__device__ __forceinline__ void ldsm4(uint32_t addr, uint32_t* a) {
    asm volatile("ldmatrix.sync.aligned.m8n8.x4.shared.b16 {%0,%1,%2,%3}, [%4];"
                 : "=r"(a[0]), "=r"(a[1]), "=r"(a[2]), "=r"(a[3]) : "r"(addr));
}
__device__ __forceinline__ void mma_f16(float* d, const uint32_t* a, const uint32_t* b) {
    asm volatile(
        "mma.sync.aligned.m16n8k16.row.col.f32.f16.f16.f32 "
        "{%0,%1,%2,%3}, {%4,%5,%6,%7}, {%8,%9}, {%0,%1,%2,%3};"
        : "+f"(d[0]), "+f"(d[1]), "+f"(d[2]), "+f"(d[3])
        : "r"(a[0]), "r"(a[1]), "r"(a[2]), "r"(a[3]), "r"(b[0]), "r"(b[1]));
}
__device__ __forceinline__ uint32_t h2bits(__half2 h) {
    return *reinterpret_cast<uint32_t*>(&h);
}
__device__ __forceinline__ uint2 cvt2h(float4 v) {
    uint2 u;
    u.x = h2bits(__floats2half2_rn(v.x, v.y));
    u.y = h2bits(__floats2half2_rn(v.z, v.w));
    return u;
}
__device__ __forceinline__ void red2(float* p, float a, float b) {
    asm volatile("red.global.add.v2.f32 [%0], {%1, %2};"
                 :: "l"(p), "f"(a), "f"(b) : "memory");
}

// ---------------- gate (fp32 exact) + co-scheduled out-zeroing ----------------
// blocks [0, NB/4): gating. blocks [NB/4, NB/4+ZB): zero `out` (16MB).
// Control-state (counters/tickets) is reset by the PREVIOUS moe_gemm's last
// CTA, so gate's atomics never race a reset.
__global__ __launch_bounds__(128) void gate_kernel(const float* __restrict__ x,
                                                   const float* __restrict__ gw,
                                                   float* __restrict__ out) {
    if (blockIdx.x >= NB / 4) {
        int c = blockIdx.x - NB / 4;
        float4* o4 = (float4*)out;
        int base = c * 128 + threadIdx.x;
        const int STRIDE = ZB * 128;
        #pragma unroll 8
        for (int i = 0; i < (NB * DOUT / 4) / (ZB * 128); ++i)
            o4[base + i * STRIDE] = make_float4(0.f, 0.f, 0.f, 0.f);
        return;
    }

    __shared__ float xs[4][DI];
    __shared__ float sc[4][NE];
    __shared__ int s_last;
    int t0 = blockIdx.x * 4;

    const float4* xsrc = (const float4*)(x + (size_t)t0 * DI);
    float4* xd = (float4*)&xs[0][0];
    #pragma unroll 4
    for (int i = threadIdx.x; i < 4 * DI / 4; i += 128) xd[i] = xsrc[i];
    __syncthreads();

    int warp = threadIdx.x >> 5, lane = threadIdx.x & 31;
    for (int e = warp * 4; e < warp * 4 + 4; ++e) {
        float s0 = 0.f, s1 = 0.f, s2 = 0.f, s3 = 0.f;
        for (int i = lane; i < DI; i += 32) {
            float g = gw[e * DI + i];
            s0 += xs[0][i] * g; s1 += xs[1][i] * g;
            s2 += xs[2][i] * g; s3 += xs[3][i] * g;
        }
        #pragma unroll
        for (int o = 16; o > 0; o >>= 1) {
            s0 += __shfl_xor_sync(0xffffffffu, s0, o);
            s1 += __shfl_xor_sync(0xffffffffu, s1, o);
            s2 += __shfl_xor_sync(0xffffffffu, s2, o);
            s3 += __shfl_xor_sync(0xffffffffu, s3, o);
        }
        if (lane == 0) { sc[0][e] = s0; sc[1][e] = s1; sc[2][e] = s2; sc[3][e] = s3; }
    }
    __syncthreads();

    if (threadIdx.x < 4) {
        int tt = threadIdx.x;
        int tok = t0 + tt;
        float bv = -1e30f; int bi = 0;
        #pragma unroll
        for (int e = 0; e < NE; ++e) {
            float v = sc[tt][e];
            if (v > bv) { bv = v; bi = e; }
        }
        float bv2 = -1e30f; int bi2 = 0;
        #pragma unroll
        for (int e = 0; e < NE; ++e) {
            if (e == bi) continue;
            float v = sc[tt][e];
            if (v > bv2) { bv2 = v; bi2 = e; }
        }
        float e2 = expf(bv2 - bv);
        float inv = 1.0f / (1.0f + e2);
        g_tidx[tok * 2 + 0] = bi;  g_tw[tok * 2 + 0] = inv;
        g_tidx[tok * 2 + 1] = bi2; g_tw[tok * 2 + 1] = e2 * inv;
        atomicAdd(&g_counts[bi], 1);
        atomicAdd(&g_counts[bi2], 1);
    }

    // last finished gate block computes prefix sums + tile table
    __threadfence();
    __syncthreads();
    if (threadIdx.x == 0)
        s_last = (atomicAdd(&g_gatefin, 1) == NB / 4 - 1) ? 1 : 0;
    __syncthreads();
    if (s_last && threadIdx.x == 0) {
        int s = 0;
        #pragma unroll
        for (int e = 0; e < NE; ++e) { g_off[e] = s; s += g_counts[e]; }
        g_off[NE] = s;
        int nt = 0;
        for (int e = 0; e < NE; ++e)
            for (int m = g_off[e]; m < g_off[e + 1]; m += 128) {
                g_tile_e[nt] = e; g_tile_m[nt] = m; ++nt;
            }
        for (; nt < MAXT; ++nt) g_tile_e[nt] = -1;
    }
}

// ---------------- scatter (two-level, low contention) -------------------------
__global__ __launch_bounds__(256) void scatter_kernel() {
    __shared__ int lcnt[NE];
    __shared__ int lbase[NE];
    int tid = threadIdx.x;
    int tok = blockIdx.x * 256 + tid;
    if (tid < NE) lcnt[tid] = 0;
    __syncthreads();
    int e0 = g_tidx[tok * 2 + 0], e1 = g_tidx[tok * 2 + 1];
    int r0 = atomicAdd(&lcnt[e0], 1);
    int r1 = atomicAdd(&lcnt[e1], 1);
    __syncthreads();
    if (tid < NE) lbase[tid] = atomicAdd(&g_cursor[tid], lcnt[tid]);
    __syncthreads();
    g_perm[g_off[e0] + lbase[e0] + r0] = tok * 2 + 0;
    g_perm[g_off[e1] + lbase[e1] + r1] = tok * 2 + 1;
}

// ---------------- GEMM tile body (R6 core, frozen) ----------------------------
#define TS 40
#define ABUF_H (128 * TS)
#define STAGE_H (2 * ABUF_H)
#define GEMM_SMEM (2 * STAGE_H * 2)   // 40960 bytes

template <int K, int NTOT, int MODE>
__device__ __forceinline__ void process_tile(
    __half* smh, float* bias_s,
    int e, int m0, int mEnd, int n0,
    const float* __restrict__ Ap, const float* __restrict__ W,
    const float* __restrict__ bias, float* __restrict__ out)
{
    const int NC = K / 32;
    int tid = threadIdx.x, lane = tid & 31, wid = tid >> 5;
    int mw = (wid >> 2) * 64;
    int nw = (wid & 3) * 32;

    if (tid < 128) bias_s[tid] = bias[e * NTOT + n0 + tid];

    int brow = tid >> 3, bc4 = tid & 7;
    const float* bP[4];
    int bOff[4];
    #pragma unroll
    for (int i = 0; i < 4; ++i) {
        int row = brow + 32 * i;
        bP[i] = W + (size_t)e * NTOT * K + (size_t)(n0 + row) * K + bc4 * 4;
        bOff[i] = row * TS + bc4 * 4;
    }

    const float* aP[4];
    const __half* aPh[2];
    int aOff[4], aOffH[2];
    if (MODE == 0) {
        #pragma unroll
        for (int i = 0; i < 4; ++i) {
            int row = brow + 32 * i;
            int gRow = m0 + row;
            int cRow = (gRow < mEnd) ? gRow : m0;
            int pair = g_perm[cRow];
            aP[i] = Ap + (size_t)(pair >> 1) * K + bc4 * 4;
            aOff[i] = row * TS + bc4 * 4;
        }
    } else {
        int arow = tid >> 2, aseg = tid & 3;
        #pragma unroll
        for (int i = 0; i < 2; ++i) {
            int row = arow + 64 * i;
            int gRow = m0 + row;
            int cRow = (gRow < mEnd) ? gRow : m0;
            aPh[i] = g_h + (size_t)cRow * K + aseg * 8;
            aOffH[i] = row * TS + aseg * 8;
        }
    }

    uint32_t sb = (uint32_t)__cvta_generic_to_shared(smh);
    uint32_t aAddrBase = sb + (uint32_t)(((mw + (lane & 15)) * TS + (lane >> 4) * 8) * 2);
    int bg = lane >> 3;
    int nblk = bg >> 1, khalf = bg & 1;
    uint32_t bAddrBase = sb + (uint32_t)((ABUF_H +
        (nw + nblk * 8 + (lane & 7)) * TS + khalf * 8) * 2);

    float acc[4][4][4];
    #pragma unroll
    for (int mi = 0; mi < 4; ++mi)
        #pragma unroll
        for (int ni = 0; ni < 4; ++ni)
            #pragma unroll
            for (int j = 0; j < 4; ++j) acc[mi][ni][j] = 0.f;

    float4 pb[4];
    float4 pa[4];
    uint4 qa[2];

    #pragma unroll
    for (int i = 0; i < 4; ++i) pb[i] = *(const float4*)(bP[i]);
    if (MODE == 0) {
        #pragma unroll
        for (int i = 0; i < 4; ++i) pa[i] = *(const float4*)(aP[i]);
    } else {
        #pragma unroll
        for (int i = 0; i < 2; ++i) qa[i] = *(const uint4*)(aPh[i]);
    }
    {
        __half* sA = smh;
        __half* sB = smh + ABUF_H;
        #pragma unroll
        for (int i = 0; i < 4; ++i) {
            uint2 u = cvt2h(pb[i]);
            *(uint2*)(sB + bOff[i]) = u;
        }
        if (MODE == 0) {
            #pragma unroll
            for (int i = 0; i < 4; ++i) {
                uint2 u = cvt2h(pa[i]);
                *(uint2*)(sA + aOff[i]) = u;
            }
        } else {
            #pragma unroll
            for (int i = 0; i < 2; ++i) *(uint4*)(sA + aOffH[i]) = qa[i];
        }
    }
    __syncthreads();

    for (int s = 0; s < NC; ++s) {
        int b = s & 1;
        if (s + 1 < NC) {
            #pragma unroll
            for (int i = 0; i < 4; ++i) pb[i] = *(const float4*)(bP[i] + (s + 1) * 32);
            if (MODE == 0) {
                #pragma unroll
                for (int i = 0; i < 4; ++i) pa[i] = *(const float4*)(aP[i] + (s + 1) * 32);
            } else {
                #pragma unroll
                for (int i = 0; i < 2; ++i) qa[i] = *(const uint4*)(aPh[i] + (s + 1) * 32);
            }
        }
        uint32_t aA = aAddrBase + (uint32_t)(b * STAGE_H * 2);
        uint32_t bA = bAddrBase + (uint32_t)(b * STAGE_H * 2);
        #pragma unroll
        for (int ks = 0; ks < 2; ++ks) {
            uint32_t af[4][4];
            #pragma unroll
            for (int mi = 0; mi < 4; ++mi)
                ldsm4(aA + mi * (16 * TS * 2) + ks * 32, af[mi]);
            uint32_t bfr[8];
            #pragma unroll
            for (int ni2 = 0; ni2 < 2; ++ni2)
                ldsm4(bA + ni2 * (16 * TS * 2) + ks * 32, &bfr[ni2 * 4]);
            #pragma unroll
            for (int mi = 0; mi < 4; ++mi)
                #pragma unroll
                for (int ni = 0; ni < 4; ++ni)
                    mma_f16(acc[mi][ni], af[mi], &bfr[ni * 2]);
        }
        if (s + 1 < NC) {
            int nb = b ^ 1;
            __half* sA = smh + nb * STAGE_H;
            __half* sB = sA + ABUF_H;
            #pragma unroll
            for (int i = 0; i < 4; ++i) {
                uint2 u = cvt2h(pb[i]);
                *(uint2*)(sB + bOff[i]) = u;
            }
            if (MODE == 0) {
                #pragma unroll
                for (int i = 0; i < 4; ++i) {
                    uint2 u = cvt2h(pa[i]);
                    *(uint2*)(sA + aOff[i]) = u;
                }
            } else {
                #pragma unroll
                for (int i = 0; i < 2; ++i) *(uint4*)(sA + aOffH[i]) = qa[i];
            }
            __syncthreads();
        }
    }

    int r4 = lane >> 2, cc = (lane & 3) * 2;
    #pragma unroll
    for (int mi = 0; mi < 4; ++mi) {
        int row0 = m0 + mw + mi * 16 + r4;
        int row1 = row0 + 8;
        bool v0 = row0 < mEnd, v1 = row1 < mEnd;
        if (MODE == 0) {
            __half* C0 = g_h + (size_t)row0 * NTOT + n0;
            __half* C1 = g_h + (size_t)row1 * NTOT + n0;
            #pragma unroll
            for (int ni = 0; ni < 4; ++ni) {
                int col = nw + ni * 8 + cc;
                float bb0 = bias_s[col], bb1 = bias_s[col + 1];
                const float* d = acc[mi][ni];
                if (v0) {
                    __half2 h = __floats2half2_rn(fmaxf(d[0] + bb0, 0.f),
                                                  fmaxf(d[1] + bb1, 0.f));
                    *(__half2*)&C0[col] = h;
                }
                if (v1) {
                    __half2 h = __floats2half2_rn(fmaxf(d[2] + bb0, 0.f),
                                                  fmaxf(d[3] + bb1, 0.f));
                    *(__half2*)&C1[col] = h;
                }
            }
        } else {
            int p0 = 0, p1 = 0;
            float w0 = 0.f, w1 = 0.f;
            if (v0) { p0 = g_perm[row0]; w0 = g_tw[p0]; }
            if (v1) { p1 = g_perm[row1]; w1 = g_tw[p1]; }
            float* O0 = out + (size_t)(p0 >> 1) * DOUT + n0;
            float* O1 = out + (size_t)(p1 >> 1) * DOUT + n0;
            #pragma unroll
            for (int ni = 0; ni < 4; ++ni) {
                int col = nw + ni * 8 + cc;
                float bb0 = bias_s[col], bb1 = bias_s[col + 1];
                const float* d = acc[mi][ni];
                if (v0) red2(O0 + col, (d[0] + bb0) * w0, (d[1] + bb1) * w0);
                if (v1) red2(O1 + col, (d[2] + bb0) * w1, (d[3] + bb1) * w1);
            }
        }
    }
}

// ---------------- persistent fused GEMM1+GEMM2 --------------------------------
__global__ __launch_bounds__(256, 2) void moe_gemm(const float* __restrict__ x,
                                                   const float* __restrict__ w1,
                                                   const float* __restrict__ b1,
                                                   const float* __restrict__ w2,
                                                   const float* __restrict__ b2,
                                                   float* __restrict__ out) {
    extern __shared__ __half smh[];
    __shared__ float bias_s[128];
    __shared__ int s_t;
    int tid = threadIdx.x;

    for (;;) {
        __syncthreads();                 // smem/bias_s reuse barrier
        if (tid == 0) s_t = atomicAdd(&g_ticket, 1);
        __syncthreads();
        int t = s_t;
        if (t >= TTOT) break;

        if (t < T1TOT) {
            int mt = t / NT1, nt = t % NT1;
            int e = g_tile_e[mt];
            if (e < 0) continue;
            int m0 = g_tile_m[mt];
            int mEnd = g_off[e + 1];
            process_tile<DI, DH, 0>(smh, bias_s, e, m0, mEnd, nt * 128,
                                    x, w1, b1, nullptr);
            __threadfence();             // publish g_h stores
            __syncthreads();
            if (tid == 0) atomicAdd(&g_done[mt], 1);
        } else {
            int idx = t - T1TOT;
            int mt = idx / NT2, nt = idx % NT2;
            int e = g_tile_e[mt];
            if (e < 0) continue;
            if (tid == 0) {
                while (*(volatile int*)&g_done[mt] < NT1) {}
                __threadfence();
            }
            __syncthreads();
            int m0 = g_tile_m[mt];
            int mEnd = g_off[e + 1];
            process_tile<DH, DOUT, 1>(smh, bias_s, e, m0, mEnd, nt * 128,
                                      nullptr, w2, b2, out);
        }
    }

    // ---- exit: last CTA (all others already exited -> no pending spins)
    // resets control state for the next graph replay. First run relies on
    // zero-initialized device globals.
    if (tid == 0) {
        int f = atomicAdd(&g_finish, 1);
        if (f == NCTA - 1) {
            #pragma unroll
            for (int i = 0; i < NE; ++i) { g_counts[i] = 0; g_cursor[i] = 0; }
            for (int i = 0; i < MAXT; ++i) g_done[i] = 0;
            g_ticket = 0;
            g_gatefin = 0;
            g_finish = 0;
            __threadfence();
        }
    }
}

// ---------------- launch -----------------------------------------------------
extern "C" void kernel_launch(void* const* d_in, const int* in_sizes, int n_in,
                              void* d_out, int out_size) {
    const float* x  = (const float*)d_in[0];
    const float* gw = (const float*)d_in[1];
    const float* w1 = (const float*)d_in[2];
    const float* b1 = (const float*)d_in[3];
    const float* w2 = (const float*)d_in[4];
    const float* b2 = (const float*)d_in[5];
    float* out = (float*)d_out;

    cudaFuncSetAttribute(moe_gemm,
                         cudaFuncAttributeMaxDynamicSharedMemorySize, GEMM_SMEM);

    gate_kernel<<<NB / 4 + ZB, 128>>>(x, gw, out);
    scatter_kernel<<<NB / 256, 256>>>();
    moe_gemm<<<NCTA, 256, GEMM_SMEM>>>(x, w1, b1, w2, b2, out);
}